// round 1
// baseline (speedup 1.0000x reference)
#include <cuda_runtime.h>
#include <math.h>

#define NQ 8
#define NL 2
#define NE 16
#define NS 256          // 2^NQ
#define NB 2048
#define ND 512
#define NWIDE (NE*NS)   // 4096

// Scratch (static device globals; no runtime allocation)
__device__ float g_UrT[NE][NS][NS];   // [e][o][s]  (transposed unitary, real)
__device__ float g_UiT[NE][NS][NS];   // [e][o][s]  (transposed unitary, imag)
__device__ float g_amps[(size_t)NB * NWIDE];  // [b][e*256+o]

// ---------------------------------------------------------------------------
// Kernel 1: build per-encoder circuit unitary U_e (256x256 complex).
// Gates act on ROWS of U (left-multiplication); columns (input basis states)
// are independent, so we split the 256 columns across 16 blocks per encoder
// and keep the 256x16 slab entirely in shared memory.
// Final store is transposed: g_U*T[e][o][s] = U[s][o], so kernel 3 can load
// o-major slices coalesced.
// ---------------------------------------------------------------------------
__global__ void __launch_bounds__(256) build_unitaries(const float* __restrict__ qw)
{
    const int e    = blockIdx.y;
    const int col0 = blockIdx.x * 16;
    const int tid  = threadIdx.x;

    __shared__ float sUr[NS][16];
    __shared__ float sUi[NS][16];

    // identity init
    for (int i = tid; i < NS * 16; i += 256) {
        int s = i >> 4, c = i & 15;
        sUr[s][c] = (s == col0 + c) ? 1.f : 0.f;
        sUi[s][c] = 0.f;
    }
    __syncthreads();

    for (int l = 0; l < NL; l++) {
        // ---- Rot(phi,theta,omega) on each wire q (wire 0 = MSB) ----
        for (int q = 0; q < NQ; q++) {
            const float* w = qw + ((e * NL + l) * NQ + q) * 3;
            float phi = w[0], th = w[1], om = w[2];
            float s_, c_, sa, ca, sm, cm;
            sincosf(0.5f * th, &s_, &c_);
            sincosf(0.5f * (phi + om), &sa, &ca);
            sincosf(0.5f * (phi - om), &sm, &cm);
            // Rot = [[em*c, -f*s],[g*s, ep*c]],
            // em=exp(-i(phi+om)/2), ep=conj(em), f=exp(+i(phi-om)/2), g=conj(f)
            const float g00r =  ca * c_, g00i = -sa * c_;
            const float g01r = -cm * s_, g01i = -sm * s_;
            const float g10r =  cm * s_, g10i = -sm * s_;
            const float g11r =  ca * c_, g11i =  sa * c_;
            const int m = 1 << (NQ - 1 - q);
            for (int i = tid; i < 128 * 16; i += 256) {
                int rp = i >> 4, cc = i & 15;
                int s0 = ((rp & ~(m - 1)) << 1) | (rp & (m - 1));
                int s1 = s0 | m;
                float u0r = sUr[s0][cc], u0i = sUi[s0][cc];
                float u1r = sUr[s1][cc], u1i = sUi[s1][cc];
                sUr[s0][cc] = g00r*u0r - g00i*u0i + g01r*u1r - g01i*u1i;
                sUi[s0][cc] = g00r*u0i + g00i*u0r + g01r*u1i + g01i*u1r;
                sUr[s1][cc] = g10r*u0r - g10i*u0i + g11r*u1r - g11i*u1i;
                sUi[s1][cc] = g10r*u0i + g10i*u0r + g11r*u1i + g11i*u1r;
            }
            __syncthreads();
        }
        // ---- CNOT ring: control q -> target (q+r)%NQ, sequential ----
        const int r = (l % (NQ - 1)) + 1;
        for (int q = 0; q < NQ; q++) {
            const int cmsk = 1 << (NQ - 1 - q);
            const int tmsk = 1 << (NQ - 1 - ((q + r) % NQ));
            for (int i = tid; i < NS * 16; i += 256) {
                int s = i >> 4, cc = i & 15;
                if ((s & cmsk) && !(s & tmsk)) {
                    int s1 = s | tmsk;
                    float a = sUr[s][cc], b = sUi[s][cc];
                    sUr[s][cc] = sUr[s1][cc]; sUi[s][cc] = sUi[s1][cc];
                    sUr[s1][cc] = a;          sUi[s1][cc] = b;
                }
            }
            __syncthreads();
        }
    }

    // transposed store: [e][o][s]
    for (int i = tid; i < 16 * NS; i += 256) {
        int oc = i >> 8, s = i & 255;
        g_UrT[e][col0 + oc][s] = sUr[s][oc];
        g_UiT[e][col0 + oc][s] = sUi[s][oc];
    }
}

// ---------------------------------------------------------------------------
// Kernel 2: amps[b][e*256+o] = sum_d x[b][d] * proj_w[e][o][d]
// C[2048][4096] = X[2048,512] @ PW[4096,512]^T
// Classic 128x128 tile, BK=8, 256 threads, 8x8 per-thread microtile.
// ---------------------------------------------------------------------------
__global__ void __launch_bounds__(256) gemm_proj(const float* __restrict__ X,
                                                 const float* __restrict__ PW)
{
    __shared__ float As[8][128];
    __shared__ float Bs[8][128];
    const int tid = threadIdx.x;
    const int bm = blockIdx.y * 128;
    const int bn = blockIdx.x * 128;
    const int lr = tid >> 1;           // 0..127 tile row
    const int lk = (tid & 1) << 2;     // 0 or 4
    const int tn = (tid & 15) << 3;    // 0..120 step 8
    const int tm = (tid >> 4) << 3;    // 0..120 step 8

    const float* xg = X  + (size_t)(bm + lr) * ND + lk;
    const float* wg = PW + (size_t)(bn + lr) * ND + lk;

    float acc[8][8];
#pragma unroll
    for (int i = 0; i < 8; i++)
#pragma unroll
        for (int j = 0; j < 8; j++) acc[i][j] = 0.f;

    for (int k0 = 0; k0 < ND; k0 += 8) {
        float4 a4 = *(const float4*)(xg + k0);
        float4 b4 = *(const float4*)(wg + k0);
        As[lk + 0][lr] = a4.x; As[lk + 1][lr] = a4.y;
        As[lk + 2][lr] = a4.z; As[lk + 3][lr] = a4.w;
        Bs[lk + 0][lr] = b4.x; Bs[lk + 1][lr] = b4.y;
        Bs[lk + 2][lr] = b4.z; Bs[lk + 3][lr] = b4.w;
        __syncthreads();
#pragma unroll
        for (int kk = 0; kk < 8; kk++) {
            float a[8], b[8];
#pragma unroll
            for (int i = 0; i < 8; i++) a[i] = As[kk][tm + i];
#pragma unroll
            for (int j = 0; j < 8; j++) b[j] = Bs[kk][tn + j];
#pragma unroll
            for (int i = 0; i < 8; i++)
#pragma unroll
                for (int j = 0; j < 8; j++)
                    acc[i][j] += a[i] * b[j];
        }
        __syncthreads();
    }

    float* cg = g_amps + (size_t)(bm + tm) * NWIDE + bn + tn;
#pragma unroll
    for (int i = 0; i < 8; i++) {
        *(float4*)(cg + (size_t)i * NWIDE)     = make_float4(acc[i][0], acc[i][1], acc[i][2], acc[i][3]);
        *(float4*)(cg + (size_t)i * NWIDE + 4) = make_float4(acc[i][4], acc[i][5], acc[i][6], acc[i][7]);
    }
}

// ---------------------------------------------------------------------------
// Kernel 3: per encoder e, b-tile of 32:
//   y[b][s] = sum_o amps[b][e*256+o] * (UrT[o][s] + i UiT[o][s])   (complex)
//   p = |y|^2 ;  tot = sum_s p ;  z[b][e*8+q] = sum_s sign_q(s) p / tot
// 256 threads: lane (0..31) covers 8 s-columns each (full s range per warp),
// warp-shuffle reduction gives block-free epilogue.
// ---------------------------------------------------------------------------
__global__ void __launch_bounds__(256) qsim_reduce(float* __restrict__ out)
{
    const int e   = blockIdx.y;
    const int b0  = blockIdx.x * 32;
    const int tid = threadIdx.x;
    const int lane = tid & 31;   // s-group: s = lane*8 + j
    const int bg   = tid >> 5;   // 0..7: b rows bg*4 .. bg*4+3

    __shared__ float As[8][33];     // [kk][b] (+pad)
    __shared__ float Br[8][256];    // [kk][s]
    __shared__ float Bi[8][256];

    const float* UrTb = &g_UrT[e][0][0];
    const float* UiTb = &g_UiT[e][0][0];

    float yr[4][8], yi[4][8];
#pragma unroll
    for (int r = 0; r < 4; r++)
#pragma unroll
        for (int j = 0; j < 8; j++) { yr[r][j] = 0.f; yi[r][j] = 0.f; }

    const int bb = tid >> 3, kq = tid & 7;

    for (int k0 = 0; k0 < NS; k0 += 8) {
        // amps slab: 8k x 32b
        As[kq][bb] = g_amps[(size_t)(b0 + bb) * NWIDE + e * NS + k0 + kq];
        // unitary slabs: contiguous 2048-float copies
        const float4* srcR = (const float4*)(UrTb + k0 * NS);
        const float4* srcI = (const float4*)(UiTb + k0 * NS);
        float4* dstR = (float4*)&Br[0][0];
        float4* dstI = (float4*)&Bi[0][0];
#pragma unroll
        for (int t = 0; t < 2; t++) {
            dstR[tid + t * 256] = srcR[tid + t * 256];
            dstI[tid + t * 256] = srcI[tid + t * 256];
        }
        __syncthreads();
#pragma unroll
        for (int kk = 0; kk < 8; kk++) {
            float a[4];
#pragma unroll
            for (int r = 0; r < 4; r++) a[r] = As[kk][bg * 4 + r];
#pragma unroll
            for (int j = 0; j < 8; j++) {
                float br = Br[kk][lane * 8 + j];
                float bi = Bi[kk][lane * 8 + j];
#pragma unroll
                for (int r = 0; r < 4; r++) {
                    yr[r][j] += a[r] * br;
                    yi[r][j] += a[r] * bi;
                }
            }
        }
        __syncthreads();
    }

    // epilogue: per b-row, 9-value warp reduction (tot + 8 signed sums)
#pragma unroll
    for (int r = 0; r < 4; r++) {
        float tot = 0.f;
        float zs[8];
#pragma unroll
        for (int q = 0; q < 8; q++) zs[q] = 0.f;
#pragma unroll
        for (int j = 0; j < 8; j++) {
            int s = lane * 8 + j;
            float p = yr[r][j] * yr[r][j] + yi[r][j] * yi[r][j];
            tot += p;
#pragma unroll
            for (int q = 0; q < 8; q++)
                zs[q] += ((s >> (7 - q)) & 1) ? -p : p;
        }
#pragma unroll
        for (int off = 16; off; off >>= 1) {
            tot += __shfl_xor_sync(0xffffffffu, tot, off);
#pragma unroll
            for (int q = 0; q < 8; q++)
                zs[q] += __shfl_xor_sync(0xffffffffu, zs[q], off);
        }
        if (lane == 0) {
            float inv = 1.0f / tot;
            int b = b0 + bg * 4 + r;
            float* o = out + (size_t)b * (NE * NQ) + e * NQ;
#pragma unroll
            for (int q = 0; q < 8; q++) o[q] = zs[q] * inv;
        }
    }
}

// ---------------------------------------------------------------------------
extern "C" void kernel_launch(void* const* d_in, const int* in_sizes, int n_in,
                              void* d_out, int out_size)
{
    const float* x  = (const float*)d_in[0];   // [2048, 512]
    const float* pw = (const float*)d_in[1];   // [16, 256, 512]
    const float* qw = (const float*)d_in[2];   // [16, 2, 8, 3]
    float* out = (float*)d_out;                // [2048, 128]

    build_unitaries<<<dim3(16, NE), 256>>>(qw);
    gemm_proj<<<dim3(NWIDE / 128, NB / 128), 256>>>(x, pw);
    qsim_reduce<<<dim3(NB / 32, NE), 256>>>(out);
}

// round 4
// speedup vs baseline: 2.1957x; 2.1957x over previous
#include <cuda_runtime.h>
#include <cuda_bf16.h>
#include <math.h>
#include <stdint.h>

#define NQ 8
#define NL 2
#define NE 16
#define NS 256
#define NB 2048
#define ND 512
#define NWIDE (NE*NS)   // 4096

// ---------------- scratch (static device globals) ----------------
__device__ __nv_bfloat16 g_xh[(size_t)NB * ND];
__device__ __nv_bfloat16 g_xl[(size_t)NB * ND];
__device__ __nv_bfloat16 g_wh[(size_t)NWIDE * ND];
__device__ __nv_bfloat16 g_wl[(size_t)NWIDE * ND];
__device__ __nv_bfloat16 g_ah[(size_t)NB * NWIDE];
__device__ __nv_bfloat16 g_al[(size_t)NB * NWIDE];
__device__ __nv_bfloat16 g_urh[NE * NS * NS];   // [e][s][o]
__device__ __nv_bfloat16 g_url[NE * NS * NS];
__device__ __nv_bfloat16 g_uih[NE * NS * NS];
__device__ __nv_bfloat16 g_uil[NE * NS * NS];

// ---------------- mma.sync m16n8k16 bf16 (sm_80+, works on compute_100) ----
__device__ __forceinline__ void mma_bf16(float* d, const uint32_t* a, const uint32_t* b) {
    asm volatile(
        "mma.sync.aligned.m16n8k16.row.col.f32.bf16.bf16.f32 "
        "{%0,%1,%2,%3}, {%4,%5,%6,%7}, {%8,%9}, {%0,%1,%2,%3};"
        : "+f"(d[0]), "+f"(d[1]), "+f"(d[2]), "+f"(d[3])
        : "r"(a[0]), "r"(a[1]), "r"(a[2]), "r"(a[3]), "r"(b[0]), "r"(b[1]));
}

#define PITCHB 144   // smem row pitch in bytes (72 bf16) -> conflict-free frags

// ---------------------------------------------------------------------------
// Kernel 0: split fp32 -> bf16 hi/lo
// ---------------------------------------------------------------------------
__device__ __forceinline__ void split4(const float* __restrict__ src,
                                       __nv_bfloat16* hi, __nv_bfloat16* lo, int i)
{
    float4 v = ((const float4*)src)[i];
    __nv_bfloat16 h0 = __float2bfloat16_rn(v.x), h1 = __float2bfloat16_rn(v.y);
    __nv_bfloat16 h2 = __float2bfloat16_rn(v.z), h3 = __float2bfloat16_rn(v.w);
    __nv_bfloat162* hp = (__nv_bfloat162*)hi;
    __nv_bfloat162* lp = (__nv_bfloat162*)lo;
    hp[2*i]   = __nv_bfloat162(h0, h1);
    hp[2*i+1] = __nv_bfloat162(h2, h3);
    lp[2*i]   = __nv_bfloat162(__float2bfloat16_rn(v.x - __bfloat162float(h0)),
                               __float2bfloat16_rn(v.y - __bfloat162float(h1)));
    lp[2*i+1] = __nv_bfloat162(__float2bfloat16_rn(v.z - __bfloat162float(h2)),
                               __float2bfloat16_rn(v.w - __bfloat162float(h3)));
}

__global__ void __launch_bounds__(256) split_x(const float* __restrict__ src)
{
    int i = blockIdx.x * 256 + threadIdx.x;
    if (i < NB * ND / 4) split4(src, g_xh, g_xl, i);
}
__global__ void __launch_bounds__(256) split_w(const float* __restrict__ src)
{
    int i = blockIdx.x * 256 + threadIdx.x;
    if (i < NWIDE * ND / 4) split4(src, g_wh, g_wl, i);
}

// ---------------------------------------------------------------------------
// Kernel 1: build per-encoder unitary; store bf16 hi/lo at [e][s][o]
// ---------------------------------------------------------------------------
__global__ void __launch_bounds__(256) build_unitaries(const float* __restrict__ qw)
{
    const int e    = blockIdx.y;
    const int col0 = blockIdx.x * 16;
    const int tid  = threadIdx.x;

    __shared__ float sUr[NS][16];
    __shared__ float sUi[NS][16];

    for (int i = tid; i < NS * 16; i += 256) {
        int s = i >> 4, c = i & 15;
        sUr[s][c] = (s == col0 + c) ? 1.f : 0.f;
        sUi[s][c] = 0.f;
    }
    __syncthreads();

    for (int l = 0; l < NL; l++) {
        for (int q = 0; q < NQ; q++) {
            const float* w = qw + ((e * NL + l) * NQ + q) * 3;
            float phi = w[0], th = w[1], om = w[2];
            float s_, c_, sa, ca, sm, cm;
            sincosf(0.5f * th, &s_, &c_);
            sincosf(0.5f * (phi + om), &sa, &ca);
            sincosf(0.5f * (phi - om), &sm, &cm);
            const float g00r =  ca * c_, g00i = -sa * c_;
            const float g01r = -cm * s_, g01i = -sm * s_;
            const float g10r =  cm * s_, g10i = -sm * s_;
            const float g11r =  ca * c_, g11i =  sa * c_;
            const int m = 1 << (NQ - 1 - q);
            for (int i = tid; i < 128 * 16; i += 256) {
                int rp = i >> 4, cc = i & 15;
                int s0 = ((rp & ~(m - 1)) << 1) | (rp & (m - 1));
                int s1 = s0 | m;
                float u0r = sUr[s0][cc], u0i = sUi[s0][cc];
                float u1r = sUr[s1][cc], u1i = sUi[s1][cc];
                sUr[s0][cc] = g00r*u0r - g00i*u0i + g01r*u1r - g01i*u1i;
                sUi[s0][cc] = g00r*u0i + g00i*u0r + g01r*u1i + g01i*u1r;
                sUr[s1][cc] = g10r*u0r - g10i*u0i + g11r*u1r - g11i*u1i;
                sUi[s1][cc] = g10r*u0i + g10i*u0r + g11r*u1i + g11i*u1r;
            }
            __syncthreads();
        }
        const int r = (l % (NQ - 1)) + 1;
        for (int q = 0; q < NQ; q++) {
            const int cmsk = 1 << (NQ - 1 - q);
            const int tmsk = 1 << (NQ - 1 - ((q + r) % NQ));
            for (int i = tid; i < NS * 16; i += 256) {
                int s = i >> 4, cc = i & 15;
                if ((s & cmsk) && !(s & tmsk)) {
                    int s1 = s | tmsk;
                    float a = sUr[s][cc], b = sUi[s][cc];
                    sUr[s][cc] = sUr[s1][cc]; sUi[s][cc] = sUi[s1][cc];
                    sUr[s1][cc] = a;          sUi[s1][cc] = b;
                }
            }
            __syncthreads();
        }
    }

    // store hi/lo bf16 at [e][s][col0+c]
    for (int i = tid; i < 16 * NS; i += 256) {
        int c = i >> 8, s = i & 255;
        float vr = sUr[s][c], vi = sUi[s][c];
        __nv_bfloat16 hr = __float2bfloat16_rn(vr);
        __nv_bfloat16 hi = __float2bfloat16_rn(vi);
        size_t idx = ((size_t)(e * NS) + s) * NS + col0 + c;
        g_urh[idx] = hr;
        g_url[idx] = __float2bfloat16_rn(vr - __bfloat162float(hr));
        g_uih[idx] = hi;
        g_uil[idx] = __float2bfloat16_rn(vi - __bfloat162float(hi));
    }
}

// ---------------------------------------------------------------------------
// Kernel 2: projection GEMM via mma.sync bf16x3.
// C[2048,4096] = X[2048,512] @ W[4096,512]^T ; CTA 128x128, KC=64.
// Output written as bf16 hi/lo (amps).
// ---------------------------------------------------------------------------
#define K2_AH 0
#define K2_AL (128*PITCHB)        // 18432
#define K2_BH (2*128*PITCHB)      // 36864
#define K2_BL (3*128*PITCHB)      // 55296
#define K2_SMEM (4*128*PITCHB)    // 73728

__global__ void __launch_bounds__(256) gemm_mma()
{
    extern __shared__ char sm[];
    const int tid  = threadIdx.x;
    const int lane = tid & 31, wid = tid >> 5;
    const int gid  = lane >> 2, tig = lane & 3;
    const int wm   = wid & 3,  wn  = wid >> 2;   // warp grid 4(M) x 2(N)
    const int bm   = blockIdx.y * 128, bn = blockIdx.x * 128;

    float acc[2][8][4];
#pragma unroll
    for (int mt = 0; mt < 2; mt++)
#pragma unroll
        for (int nt = 0; nt < 8; nt++)
#pragma unroll
            for (int j = 0; j < 4; j++) acc[mt][nt][j] = 0.f;

    for (int k0 = 0; k0 < ND; k0 += 64) {
#pragma unroll
        for (int it = 0; it < 4; it++) {
            int i = tid + it * 256;
            int row = i >> 3, c = i & 7;
            int d = row * PITCHB + c * 16;
            size_t ga = (size_t)(bm + row) * ND + k0 + c * 8;
            size_t gb = (size_t)(bn + row) * ND + k0 + c * 8;
            *(uint4*)(sm + K2_AH + d) = *(const uint4*)(g_xh + ga);
            *(uint4*)(sm + K2_AL + d) = *(const uint4*)(g_xl + ga);
            *(uint4*)(sm + K2_BH + d) = *(const uint4*)(g_wh + gb);
            *(uint4*)(sm + K2_BL + d) = *(const uint4*)(g_wl + gb);
        }
        __syncthreads();
#pragma unroll
        for (int kc = 0; kc < 4; kc++) {
            const int kb = (kc * 16 + 2 * tig) * 2;
            uint32_t ah[2][4], al[2][4];
#pragma unroll
            for (int mt = 0; mt < 2; mt++) {
                const char* base = sm + (wm * 32 + mt * 16 + gid) * PITCHB + kb;
                ah[mt][0] = *(const uint32_t*)(base + K2_AH);
                ah[mt][1] = *(const uint32_t*)(base + K2_AH + 8 * PITCHB);
                ah[mt][2] = *(const uint32_t*)(base + K2_AH + 16);
                ah[mt][3] = *(const uint32_t*)(base + K2_AH + 8 * PITCHB + 16);
                al[mt][0] = *(const uint32_t*)(base + K2_AL);
                al[mt][1] = *(const uint32_t*)(base + K2_AL + 8 * PITCHB);
                al[mt][2] = *(const uint32_t*)(base + K2_AL + 16);
                al[mt][3] = *(const uint32_t*)(base + K2_AL + 8 * PITCHB + 16);
            }
#pragma unroll
            for (int nt = 0; nt < 8; nt++) {
                const char* base = sm + (wn * 64 + nt * 8 + gid) * PITCHB + kb;
                uint32_t bh[2], bl[2];
                bh[0] = *(const uint32_t*)(base + K2_BH);
                bh[1] = *(const uint32_t*)(base + K2_BH + 16);
                bl[0] = *(const uint32_t*)(base + K2_BL);
                bl[1] = *(const uint32_t*)(base + K2_BL + 16);
#pragma unroll
                for (int mt = 0; mt < 2; mt++) {
                    mma_bf16(acc[mt][nt], ah[mt], bh);
                    mma_bf16(acc[mt][nt], ah[mt], bl);
                    mma_bf16(acc[mt][nt], al[mt], bh);
                }
            }
        }
        __syncthreads();
    }

    // epilogue: split fp32 accum into bf16 hi/lo amps
#pragma unroll
    for (int mt = 0; mt < 2; mt++) {
#pragma unroll
        for (int nt = 0; nt < 8; nt++) {
            int r0 = bm + wm * 32 + mt * 16 + gid;
            int n  = bn + wn * 64 + nt * 8 + 2 * tig;
            float v00 = acc[mt][nt][0], v01 = acc[mt][nt][1];
            float v10 = acc[mt][nt][2], v11 = acc[mt][nt][3];
            __nv_bfloat16 h00 = __float2bfloat16_rn(v00), h01 = __float2bfloat16_rn(v01);
            __nv_bfloat16 h10 = __float2bfloat16_rn(v10), h11 = __float2bfloat16_rn(v11);
            *(__nv_bfloat162*)(g_ah + (size_t)r0 * NWIDE + n) = __nv_bfloat162(h00, h01);
            *(__nv_bfloat162*)(g_al + (size_t)r0 * NWIDE + n) =
                __nv_bfloat162(__float2bfloat16_rn(v00 - __bfloat162float(h00)),
                               __float2bfloat16_rn(v01 - __bfloat162float(h01)));
            *(__nv_bfloat162*)(g_ah + (size_t)(r0 + 8) * NWIDE + n) = __nv_bfloat162(h10, h11);
            *(__nv_bfloat162*)(g_al + (size_t)(r0 + 8) * NWIDE + n) =
                __nv_bfloat162(__float2bfloat16_rn(v10 - __bfloat162float(h10)),
                               __float2bfloat16_rn(v11 - __bfloat162float(h11)));
        }
    }
}

// ---------------------------------------------------------------------------
// Kernel 3: per-encoder complex GEMM + fused signed reduction.
// y[b][s] = sum_o amps[b][o] * U[s][o]  (A[M=64,K=256] @ B[N=256,K=256]^T)
// p = |y|^2 -> tot + 8 signed sums -> normalized z.
// ---------------------------------------------------------------------------
#define K3_AH  0
#define K3_AL  (64*PITCHB)              // 9216
#define K3_URH (2*64*PITCHB)            // 18432
#define K3_URL (K3_URH + 256*PITCHB)    // 55296
#define K3_UIH (K3_URL + 256*PITCHB)    // 92160
#define K3_UIL (K3_UIH + 256*PITCHB)    // 129024
#define K3_RED (K3_UIL + 256*PITCHB)    // 165888
#define K3_SMEM (K3_RED + 64*9*4)       // 168192

__global__ void __launch_bounds__(256) qsim_mma(float* __restrict__ out)
{
    extern __shared__ char sm[];
    const int tid  = threadIdx.x;
    const int lane = tid & 31, wid = tid >> 5;
    const int gid  = lane >> 2, tig = lane & 3;
    const int wm   = wid & 1,  wn  = wid >> 1;   // warp grid 2(M) x 4(N)
    const int e    = blockIdx.y;
    const int bm   = blockIdx.x * 64;

    float* red = (float*)(sm + K3_RED);
    for (int i = tid; i < 64 * 9; i += 256) red[i] = 0.f;

    float accR[2][8][4], accI[2][8][4];
#pragma unroll
    for (int mt = 0; mt < 2; mt++)
#pragma unroll
        for (int nt = 0; nt < 8; nt++)
#pragma unroll
            for (int j = 0; j < 4; j++) { accR[mt][nt][j] = 0.f; accI[mt][nt][j] = 0.f; }

    for (int k0 = 0; k0 < NS; k0 += 64) {
#pragma unroll
        for (int it = 0; it < 2; it++) {
            int i = tid + it * 256;
            int row = i >> 3, c = i & 7;
            int d = row * PITCHB + c * 16;
            size_t ga = (size_t)(bm + row) * NWIDE + e * NS + k0 + c * 8;
            *(uint4*)(sm + K3_AH + d) = *(const uint4*)(g_ah + ga);
            *(uint4*)(sm + K3_AL + d) = *(const uint4*)(g_al + ga);
        }
#pragma unroll
        for (int it = 0; it < 8; it++) {
            int i = tid + it * 256;
            int row = i >> 3, c = i & 7;
            int d = row * PITCHB + c * 16;
            size_t gu = ((size_t)(e * NS) + row) * NS + k0 + c * 8;
            *(uint4*)(sm + K3_URH + d) = *(const uint4*)(g_urh + gu);
            *(uint4*)(sm + K3_URL + d) = *(const uint4*)(g_url + gu);
            *(uint4*)(sm + K3_UIH + d) = *(const uint4*)(g_uih + gu);
            *(uint4*)(sm + K3_UIL + d) = *(const uint4*)(g_uil + gu);
        }
        __syncthreads();
#pragma unroll
        for (int kc = 0; kc < 4; kc++) {
            const int kb = (kc * 16 + 2 * tig) * 2;
            uint32_t ah[2][4], al[2][4];
#pragma unroll
            for (int mt = 0; mt < 2; mt++) {
                const char* base = sm + (wm * 32 + mt * 16 + gid) * PITCHB + kb;
                ah[mt][0] = *(const uint32_t*)(base + K3_AH);
                ah[mt][1] = *(const uint32_t*)(base + K3_AH + 8 * PITCHB);
                ah[mt][2] = *(const uint32_t*)(base + K3_AH + 16);
                ah[mt][3] = *(const uint32_t*)(base + K3_AH + 8 * PITCHB + 16);
                al[mt][0] = *(const uint32_t*)(base + K3_AL);
                al[mt][1] = *(const uint32_t*)(base + K3_AL + 8 * PITCHB);
                al[mt][2] = *(const uint32_t*)(base + K3_AL + 16);
                al[mt][3] = *(const uint32_t*)(base + K3_AL + 8 * PITCHB + 16);
            }
#pragma unroll
            for (int nt = 0; nt < 8; nt++) {
                const char* base = sm + (wn * 64 + nt * 8 + gid) * PITCHB + kb;
                uint32_t urh[2], url[2], uih[2], uil[2];
                urh[0] = *(const uint32_t*)(base + K3_URH);
                urh[1] = *(const uint32_t*)(base + K3_URH + 16);
                url[0] = *(const uint32_t*)(base + K3_URL);
                url[1] = *(const uint32_t*)(base + K3_URL + 16);
                uih[0] = *(const uint32_t*)(base + K3_UIH);
                uih[1] = *(const uint32_t*)(base + K3_UIH + 16);
                uil[0] = *(const uint32_t*)(base + K3_UIL);
                uil[1] = *(const uint32_t*)(base + K3_UIL + 16);
#pragma unroll
                for (int mt = 0; mt < 2; mt++) {
                    mma_bf16(accR[mt][nt], ah[mt], urh);
                    mma_bf16(accR[mt][nt], ah[mt], url);
                    mma_bf16(accR[mt][nt], al[mt], urh);
                    mma_bf16(accI[mt][nt], ah[mt], uih);
                    mma_bf16(accI[mt][nt], ah[mt], uil);
                    mma_bf16(accI[mt][nt], al[mt], uih);
                }
            }
        }
        __syncthreads();
    }

    // fused epilogue: p = |y|^2; 9-way signed reduction
#pragma unroll
    for (int mt = 0; mt < 2; mt++) {
#pragma unroll
        for (int half = 0; half < 2; half++) {
            int rowL = wm * 32 + mt * 16 + gid + half * 8;
            float part[9];
#pragma unroll
            for (int j = 0; j < 9; j++) part[j] = 0.f;
#pragma unroll
            for (int nt = 0; nt < 8; nt++) {
#pragma unroll
                for (int j = 0; j < 2; j++) {
                    float vr = accR[mt][nt][half * 2 + j];
                    float vi = accI[mt][nt][half * 2 + j];
                    float p = vr * vr + vi * vi;
                    int s = wn * 64 + nt * 8 + 2 * tig + j;
                    part[0] += p;
#pragma unroll
                    for (int q = 0; q < 8; q++)
                        part[1 + q] += ((s >> (7 - q)) & 1) ? -p : p;
                }
            }
#pragma unroll
            for (int j = 0; j < 9; j++) {
                part[j] += __shfl_xor_sync(0xffffffffu, part[j], 1);
                part[j] += __shfl_xor_sync(0xffffffffu, part[j], 2);
            }
            if (tig == 0) {
#pragma unroll
                for (int j = 0; j < 9; j++)
                    atomicAdd(&red[rowL * 9 + j], part[j]);
            }
        }
    }
    __syncthreads();
    if (tid < 64) {
        float inv = 1.0f / red[tid * 9];
        float* o = out + (size_t)(bm + tid) * (NE * NQ) + e * NQ;
#pragma unroll
        for (int q = 0; q < 8; q++) o[q] = red[tid * 9 + 1 + q] * inv;
    }
}

// ---------------------------------------------------------------------------
extern "C" void kernel_launch(void* const* d_in, const int* in_sizes, int n_in,
                              void* d_out, int out_size)
{
    const float* x  = (const float*)d_in[0];
    const float* pw = (const float*)d_in[1];
    const float* qw = (const float*)d_in[2];
    float* out = (float*)d_out;

    cudaFuncSetAttribute(gemm_mma, cudaFuncAttributeMaxDynamicSharedMemorySize, K2_SMEM);
    cudaFuncSetAttribute(qsim_mma, cudaFuncAttributeMaxDynamicSharedMemorySize, K3_SMEM);

    split_x<<<(NB * ND / 4 + 255) / 256, 256>>>(x);
    split_w<<<(NWIDE * ND / 4 + 255) / 256, 256>>>(pw);
    build_unitaries<<<dim3(16, NE), 256>>>(qw);
    gemm_mma<<<dim3(NWIDE / 128, NB / 128), 256, K2_SMEM>>>();
    qsim_mma<<<dim3(NB / 64, NE), 256, K3_SMEM>>>(out);
}

// round 5
// speedup vs baseline: 2.6894x; 1.2248x over previous
#include <cuda_runtime.h>
#include <cuda_bf16.h>
#include <math.h>
#include <stdint.h>

#define NQ 8
#define NL 2
#define NE 16
#define NS 256
#define NB 2048
#define ND 512
#define NWIDE (NE*NS)   // 4096

// ---------------- scratch (static device globals) ----------------
__device__ __nv_bfloat16 g_xh[(size_t)NB * ND];
__device__ __nv_bfloat16 g_xl[(size_t)NB * ND];
__device__ __nv_bfloat16 g_wh[(size_t)NWIDE * ND];
__device__ __nv_bfloat16 g_wl[(size_t)NWIDE * ND];
__device__ __nv_bfloat16 g_ah[(size_t)NB * NWIDE];
__device__ __nv_bfloat16 g_al[(size_t)NB * NWIDE];
__device__ __nv_bfloat16 g_urh[NE * NS * NS];   // [e][s][o]
__device__ __nv_bfloat16 g_url[NE * NS * NS];
__device__ __nv_bfloat16 g_uih[NE * NS * NS];
__device__ __nv_bfloat16 g_uil[NE * NS * NS];
__device__ float g_gates[NE * NL * NQ * 8];

// ---------------- mma.sync m16n8k16 bf16 ----------------
__device__ __forceinline__ void mma_bf16(float* d, const uint32_t* a, const uint32_t* b) {
    asm volatile(
        "mma.sync.aligned.m16n8k16.row.col.f32.bf16.bf16.f32 "
        "{%0,%1,%2,%3}, {%4,%5,%6,%7}, {%8,%9}, {%0,%1,%2,%3};"
        : "+f"(d[0]), "+f"(d[1]), "+f"(d[2]), "+f"(d[3])
        : "r"(a[0]), "r"(a[1]), "r"(a[2]), "r"(a[3]), "r"(b[0]), "r"(b[1]));
}

#define CP16(dst, src) \
    asm volatile("cp.async.cg.shared.global [%0], [%1], 16;" :: "r"(dst), "l"(src))
#define CP_COMMIT() asm volatile("cp.async.commit_group;")
#define CP_WAIT1()  asm volatile("cp.async.wait_group 1;")
#define CP_WAIT0()  asm volatile("cp.async.wait_group 0;")

#define PITCHB 144   // K2 smem row pitch bytes (64 bf16 + pad)
#define P3 80        // K3 smem row pitch bytes (32 bf16 + pad)

// ---------------------------------------------------------------------------
// Kernel 0: split fp32 -> bf16 hi/lo
// ---------------------------------------------------------------------------
__device__ __forceinline__ void split4(const float* __restrict__ src,
                                       __nv_bfloat16* hi, __nv_bfloat16* lo, int i)
{
    float4 v = ((const float4*)src)[i];
    __nv_bfloat16 h0 = __float2bfloat16_rn(v.x), h1 = __float2bfloat16_rn(v.y);
    __nv_bfloat16 h2 = __float2bfloat16_rn(v.z), h3 = __float2bfloat16_rn(v.w);
    __nv_bfloat162* hp = (__nv_bfloat162*)hi;
    __nv_bfloat162* lp = (__nv_bfloat162*)lo;
    hp[2*i]   = __nv_bfloat162(h0, h1);
    hp[2*i+1] = __nv_bfloat162(h2, h3);
    lp[2*i]   = __nv_bfloat162(__float2bfloat16_rn(v.x - __bfloat162float(h0)),
                               __float2bfloat16_rn(v.y - __bfloat162float(h1)));
    lp[2*i+1] = __nv_bfloat162(__float2bfloat16_rn(v.z - __bfloat162float(h2)),
                               __float2bfloat16_rn(v.w - __bfloat162float(h3)));
}

__global__ void __launch_bounds__(256) split_x(const float* __restrict__ src)
{
    int i = blockIdx.x * 256 + threadIdx.x;
    if (i < NB * ND / 4) split4(src, g_xh, g_xl, i);
}
__global__ void __launch_bounds__(256) split_w(const float* __restrict__ src)
{
    int i = blockIdx.x * 256 + threadIdx.x;
    if (i < NWIDE * ND / 4) split4(src, g_wh, g_wl, i);
}

// ---------------------------------------------------------------------------
// Kernel 1a: precompute gate 2x2 matrices (8 floats each)
// ---------------------------------------------------------------------------
__global__ void gate_prep(const float* __restrict__ qw)
{
    int g = threadIdx.x;
    if (g >= NE * NL * NQ) return;
    const float* w = qw + g * 3;
    float phi = w[0], th = w[1], om = w[2];
    float s_, c_, sa, ca, sm2, cm2;
    sincosf(0.5f * th, &s_, &c_);
    sincosf(0.5f * (phi + om), &sa, &ca);
    sincosf(0.5f * (phi - om), &sm2, &cm2);
    float* o = g_gates + g * 8;
    o[0] =  ca * c_;  o[1] = -sa * c_;   // g00
    o[2] = -cm2 * s_; o[3] = -sm2 * s_;  // g01
    o[4] =  cm2 * s_; o[5] = -sm2 * s_;  // g10
    o[6] =  ca * c_;  o[7] =  sa * c_;   // g11
}

// ---------------------------------------------------------------------------
// Kernel 1b: register-resident statevector simulator.
// One warp per unitary column (basis state c): 256 complex amps = 8/lane.
// s = (j<<5) | lane. Wires 0-2 pair across regs; wires 3-7 via shfl.xor.
// ---------------------------------------------------------------------------
__global__ void __launch_bounds__(256) build_unitaries_reg()
{
    const int e    = blockIdx.y;
    const int w    = threadIdx.x >> 5;
    const int c    = blockIdx.x * 8 + w;
    const int lane = threadIdx.x & 31;

    float ar[8], ai[8];
#pragma unroll
    for (int j = 0; j < 8; j++) {
        ar[j] = (((j << 5) | lane) == c) ? 1.f : 0.f;
        ai[j] = 0.f;
    }

#pragma unroll
    for (int l = 0; l < NL; l++) {
#pragma unroll
        for (int q = 0; q < NQ; q++) {
            const float4* gp = (const float4*)&g_gates[(((e * NL) + l) * NQ + q) * 8];
            float4 gA = gp[0], gB = gp[1];
            const float g00r = gA.x, g00i = gA.y, g01r = gA.z, g01i = gA.w;
            const float g10r = gB.x, g10i = gB.y, g11r = gB.z, g11i = gB.w;
            const int m = 1 << (7 - q);
            if (m >= 32) {
                const int jm = m >> 5;
#pragma unroll
                for (int j = 0; j < 8; j++) if (!(j & jm)) {
                    int j2 = j | jm;
                    float u0r = ar[j], u0i = ai[j], u1r = ar[j2], u1i = ai[j2];
                    ar[j]  = g00r*u0r - g00i*u0i + g01r*u1r - g01i*u1i;
                    ai[j]  = g00r*u0i + g00i*u0r + g01r*u1i + g01i*u1r;
                    ar[j2] = g10r*u0r - g10i*u0i + g11r*u1r - g11i*u1i;
                    ai[j2] = g10r*u0i + g10i*u0r + g11r*u1i + g11i*u1r;
                }
            } else {
                const bool hib = (lane & m) != 0;
                const float c0r = hib ? g10r : g00r, c0i = hib ? g10i : g00i;
                const float c1r = hib ? g11r : g01r, c1i = hib ? g11i : g01i;
#pragma unroll
                for (int j = 0; j < 8; j++) {
                    float br = __shfl_xor_sync(0xffffffffu, ar[j], m);
                    float bi = __shfl_xor_sync(0xffffffffu, ai[j], m);
                    float u0r = hib ? br : ar[j], u0i = hib ? bi : ai[j];
                    float u1r = hib ? ar[j] : br, u1i = hib ? ai[j] : bi;
                    ar[j] = c0r*u0r - c0i*u0i + c1r*u1r - c1i*u1i;
                    ai[j] = c0r*u0i + c0i*u0r + c1r*u1i + c1i*u1r;
                }
            }
        }
        const int r = (l % (NQ - 1)) + 1;
#pragma unroll
        for (int q = 0; q < NQ; q++) {
            const int cm = 1 << (7 - q);
            const int tm = 1 << (7 - ((q + r) % NQ));
            if (tm >= 32) {
                const int jt = tm >> 5;
#pragma unroll
                for (int j = 0; j < 8; j++) if (!(j & jt)) {
                    int j2 = j | jt;
                    bool cond = ((((j << 5) | lane) & cm) != 0);
                    float t0 = ar[j], t1 = ar[j2];
                    ar[j] = cond ? t1 : t0; ar[j2] = cond ? t0 : t1;
                    t0 = ai[j]; t1 = ai[j2];
                    ai[j] = cond ? t1 : t0; ai[j2] = cond ? t0 : t1;
                }
            } else {
#pragma unroll
                for (int j = 0; j < 8; j++) {
                    float br = __shfl_xor_sync(0xffffffffu, ar[j], tm);
                    float bi = __shfl_xor_sync(0xffffffffu, ai[j], tm);
                    bool cond = ((((j << 5) | lane) & cm) != 0);
                    ar[j] = cond ? br : ar[j];
                    ai[j] = cond ? bi : ai[j];
                }
            }
        }
    }

    // stage bf16 hi/lo, transpose, store coalesced at [e][s][c]
    __shared__ __nv_bfloat16 st[4][NS][8];
#pragma unroll
    for (int j = 0; j < 8; j++) {
        int s = (j << 5) | lane;
        __nv_bfloat16 hr = __float2bfloat16_rn(ar[j]);
        __nv_bfloat16 hi = __float2bfloat16_rn(ai[j]);
        st[0][s][w] = hr;
        st[1][s][w] = __float2bfloat16_rn(ar[j] - __bfloat162float(hr));
        st[2][s][w] = hi;
        st[3][s][w] = __float2bfloat16_rn(ai[j] - __bfloat162float(hi));
    }
    __syncthreads();
    const int s = threadIdx.x;
    size_t idx = ((size_t)(e * NS) + s) * NS + blockIdx.x * 8;
    *(uint4*)(g_urh + idx) = *(const uint4*)&st[0][s][0];
    *(uint4*)(g_url + idx) = *(const uint4*)&st[1][s][0];
    *(uint4*)(g_uih + idx) = *(const uint4*)&st[2][s][0];
    *(uint4*)(g_uil + idx) = *(const uint4*)&st[3][s][0];
}

// ---------------------------------------------------------------------------
// Kernel 2: projection GEMM, cp.async 2-stage pipeline, bf16x3 split.
// ---------------------------------------------------------------------------
#define K2_AH 0
#define K2_AL (128*PITCHB)
#define K2_BH (2*128*PITCHB)
#define K2_BL (3*128*PITCHB)
#define K2_STG (4*128*PITCHB)     // 73728
#define K2_SMEM (2*K2_STG)        // 147456

__global__ void __launch_bounds__(256) gemm_mma()
{
    extern __shared__ char sm[];
    const uint32_t smu = (uint32_t)__cvta_generic_to_shared(sm);
    const int tid  = threadIdx.x;
    const int lane = tid & 31, wid = tid >> 5;
    const int gid  = lane >> 2, tig = lane & 3;
    const int wm   = wid & 3,  wn  = wid >> 2;
    const int bm   = blockIdx.y * 128, bn = blockIdx.x * 128;

    float acc[2][8][4];
#pragma unroll
    for (int mt = 0; mt < 2; mt++)
#pragma unroll
        for (int nt = 0; nt < 8; nt++)
#pragma unroll
            for (int j = 0; j < 4; j++) acc[mt][nt][j] = 0.f;

    auto issue = [&](int ch, int p) {
        const int k0 = ch * 64;
        const uint32_t sb = smu + p * K2_STG;
#pragma unroll
        for (int it = 0; it < 4; it++) {
            int i = tid + it * 256;
            int row = i >> 3, cc = i & 7;
            uint32_t d = row * PITCHB + cc * 16;
            size_t ga = (size_t)(bm + row) * ND + k0 + cc * 8;
            size_t gb = (size_t)(bn + row) * ND + k0 + cc * 8;
            CP16(sb + K2_AH + d, g_xh + ga);
            CP16(sb + K2_AL + d, g_xl + ga);
            CP16(sb + K2_BH + d, g_wh + gb);
            CP16(sb + K2_BL + d, g_wl + gb);
        }
        CP_COMMIT();
    };

    issue(0, 0);
    for (int ch = 0; ch < 8; ch++) {
        if (ch + 1 < 8) { issue(ch + 1, (ch + 1) & 1); CP_WAIT1(); }
        else            { CP_WAIT0(); }
        __syncthreads();
        const char* bp = sm + (ch & 1) * K2_STG;
#pragma unroll
        for (int kc = 0; kc < 4; kc++) {
            const int kb = kc * 32 + tig * 4;
            uint32_t ah[2][4], al[2][4];
#pragma unroll
            for (int mt = 0; mt < 2; mt++) {
                const char* base = bp + (wm * 32 + mt * 16 + gid) * PITCHB + kb;
                ah[mt][0] = *(const uint32_t*)(base + K2_AH);
                ah[mt][1] = *(const uint32_t*)(base + K2_AH + 8 * PITCHB);
                ah[mt][2] = *(const uint32_t*)(base + K2_AH + 16);
                ah[mt][3] = *(const uint32_t*)(base + K2_AH + 8 * PITCHB + 16);
                al[mt][0] = *(const uint32_t*)(base + K2_AL);
                al[mt][1] = *(const uint32_t*)(base + K2_AL + 8 * PITCHB);
                al[mt][2] = *(const uint32_t*)(base + K2_AL + 16);
                al[mt][3] = *(const uint32_t*)(base + K2_AL + 8 * PITCHB + 16);
            }
#pragma unroll
            for (int nt = 0; nt < 8; nt++) {
                const char* base = bp + (wn * 64 + nt * 8 + gid) * PITCHB + kb;
                uint32_t bh[2], bl[2];
                bh[0] = *(const uint32_t*)(base + K2_BH);
                bh[1] = *(const uint32_t*)(base + K2_BH + 16);
                bl[0] = *(const uint32_t*)(base + K2_BL);
                bl[1] = *(const uint32_t*)(base + K2_BL + 16);
#pragma unroll
                for (int mt = 0; mt < 2; mt++) {
                    mma_bf16(acc[mt][nt], ah[mt], bh);
                    mma_bf16(acc[mt][nt], ah[mt], bl);
                    mma_bf16(acc[mt][nt], al[mt], bh);
                }
            }
        }
        __syncthreads();
    }

#pragma unroll
    for (int mt = 0; mt < 2; mt++) {
#pragma unroll
        for (int nt = 0; nt < 8; nt++) {
            int r0 = bm + wm * 32 + mt * 16 + gid;
            int n  = bn + wn * 64 + nt * 8 + 2 * tig;
            float v00 = acc[mt][nt][0], v01 = acc[mt][nt][1];
            float v10 = acc[mt][nt][2], v11 = acc[mt][nt][3];
            __nv_bfloat16 h00 = __float2bfloat16_rn(v00), h01 = __float2bfloat16_rn(v01);
            __nv_bfloat16 h10 = __float2bfloat16_rn(v10), h11 = __float2bfloat16_rn(v11);
            *(__nv_bfloat162*)(g_ah + (size_t)r0 * NWIDE + n) = __nv_bfloat162(h00, h01);
            *(__nv_bfloat162*)(g_al + (size_t)r0 * NWIDE + n) =
                __nv_bfloat162(__float2bfloat16_rn(v00 - __bfloat162float(h00)),
                               __float2bfloat16_rn(v01 - __bfloat162float(h01)));
            *(__nv_bfloat162*)(g_ah + (size_t)(r0 + 8) * NWIDE + n) = __nv_bfloat162(h10, h11);
            *(__nv_bfloat162*)(g_al + (size_t)(r0 + 8) * NWIDE + n) =
                __nv_bfloat162(__float2bfloat16_rn(v10 - __bfloat162float(h10)),
                               __float2bfloat16_rn(v11 - __bfloat162float(h11)));
        }
    }
}

// ---------------------------------------------------------------------------
// Kernel 3: per-encoder complex GEMM + fused reduction, cp.async 2-stage.
// KC=32 chunks so two stages fit in smem.
// ---------------------------------------------------------------------------
#define K3_AH 0
#define K3_AL  (64*P3)            // 5120
#define K3_URH (2*64*P3)          // 10240
#define K3_URL (K3_URH + 256*P3)  // 30720
#define K3_UIH (K3_URL + 256*P3)  // 51200
#define K3_UIL (K3_UIH + 256*P3)  // 71680
#define K3_STG (K3_UIL + 256*P3)  // 92160
#define K3_SMEM (2*K3_STG + 64*9*4)  // 186624

__global__ void __launch_bounds__(256) qsim_mma(float* __restrict__ out)
{
    extern __shared__ char sm[];
    const uint32_t smu = (uint32_t)__cvta_generic_to_shared(sm);
    const int tid  = threadIdx.x;
    const int lane = tid & 31, wid = tid >> 5;
    const int gid  = lane >> 2, tig = lane & 3;
    const int wm   = wid & 1,  wn  = wid >> 1;
    const int e    = blockIdx.y;
    const int bm   = blockIdx.x * 64;

    float* red = (float*)(sm + 2 * K3_STG);
    for (int i = tid; i < 64 * 9; i += 256) red[i] = 0.f;

    float accR[2][8][4], accI[2][8][4];
#pragma unroll
    for (int mt = 0; mt < 2; mt++)
#pragma unroll
        for (int nt = 0; nt < 8; nt++)
#pragma unroll
            for (int j = 0; j < 4; j++) { accR[mt][nt][j] = 0.f; accI[mt][nt][j] = 0.f; }

    auto issue = [&](int ch, int p) {
        const int k0 = ch * 32;
        const uint32_t sb = smu + p * K3_STG;
        {
            int row = tid >> 2, cc = tid & 3;
            uint32_t d = row * P3 + cc * 16;
            size_t ga = (size_t)(bm + row) * NWIDE + e * NS + k0 + cc * 8;
            CP16(sb + K3_AH + d, g_ah + ga);
            CP16(sb + K3_AL + d, g_al + ga);
        }
#pragma unroll
        for (int it = 0; it < 4; it++) {
            int i = tid + it * 256;
            int row = i >> 2, cc = i & 3;
            uint32_t d = row * P3 + cc * 16;
            size_t gu = ((size_t)(e * NS) + row) * NS + k0 + cc * 8;
            CP16(sb + K3_URH + d, g_urh + gu);
            CP16(sb + K3_URL + d, g_url + gu);
            CP16(sb + K3_UIH + d, g_uih + gu);
            CP16(sb + K3_UIL + d, g_uil + gu);
        }
        CP_COMMIT();
    };

    issue(0, 0);
    for (int ch = 0; ch < 8; ch++) {
        if (ch + 1 < 8) { issue(ch + 1, (ch + 1) & 1); CP_WAIT1(); }
        else            { CP_WAIT0(); }
        __syncthreads();
        const char* bp = sm + (ch & 1) * K3_STG;
#pragma unroll
        for (int kc = 0; kc < 2; kc++) {
            const int kb = kc * 32 + tig * 4;
            uint32_t ah[2][4], al[2][4];
#pragma unroll
            for (int mt = 0; mt < 2; mt++) {
                const char* base = bp + (wm * 32 + mt * 16 + gid) * P3 + kb;
                ah[mt][0] = *(const uint32_t*)(base + K3_AH);
                ah[mt][1] = *(const uint32_t*)(base + K3_AH + 8 * P3);
                ah[mt][2] = *(const uint32_t*)(base + K3_AH + 16);
                ah[mt][3] = *(const uint32_t*)(base + K3_AH + 8 * P3 + 16);
                al[mt][0] = *(const uint32_t*)(base + K3_AL);
                al[mt][1] = *(const uint32_t*)(base + K3_AL + 8 * P3);
                al[mt][2] = *(const uint32_t*)(base + K3_AL + 16);
                al[mt][3] = *(const uint32_t*)(base + K3_AL + 8 * P3 + 16);
            }
#pragma unroll
            for (int nt = 0; nt < 8; nt++) {
                const char* base = bp + (wn * 64 + nt * 8 + gid) * P3 + kb;
                uint32_t urh[2], url[2], uih[2], uil[2];
                urh[0] = *(const uint32_t*)(base + K3_URH);
                urh[1] = *(const uint32_t*)(base + K3_URH + 16);
                url[0] = *(const uint32_t*)(base + K3_URL);
                url[1] = *(const uint32_t*)(base + K3_URL + 16);
                uih[0] = *(const uint32_t*)(base + K3_UIH);
                uih[1] = *(const uint32_t*)(base + K3_UIH + 16);
                uil[0] = *(const uint32_t*)(base + K3_UIL);
                uil[1] = *(const uint32_t*)(base + K3_UIL + 16);
#pragma unroll
                for (int mt = 0; mt < 2; mt++) {
                    mma_bf16(accR[mt][nt], ah[mt], urh);
                    mma_bf16(accR[mt][nt], ah[mt], url);
                    mma_bf16(accR[mt][nt], al[mt], urh);
                    mma_bf16(accI[mt][nt], ah[mt], uih);
                    mma_bf16(accI[mt][nt], ah[mt], uil);
                    mma_bf16(accI[mt][nt], al[mt], uih);
                }
            }
        }
        __syncthreads();
    }

    // fused epilogue: p = |y|^2; tot + 8 signed sums; normalize
#pragma unroll
    for (int mt = 0; mt < 2; mt++) {
#pragma unroll
        for (int half = 0; half < 2; half++) {
            int rowL = wm * 32 + mt * 16 + gid + half * 8;
            float part[9];
#pragma unroll
            for (int j = 0; j < 9; j++) part[j] = 0.f;
#pragma unroll
            for (int nt = 0; nt < 8; nt++) {
#pragma unroll
                for (int j = 0; j < 2; j++) {
                    float vr = accR[mt][nt][half * 2 + j];
                    float vi = accI[mt][nt][half * 2 + j];
                    float p = vr * vr + vi * vi;
                    int s = wn * 64 + nt * 8 + 2 * tig + j;
                    part[0] += p;
#pragma unroll
                    for (int q = 0; q < 8; q++)
                        part[1 + q] += ((s >> (7 - q)) & 1) ? -p : p;
                }
            }
#pragma unroll
            for (int j = 0; j < 9; j++) {
                part[j] += __shfl_xor_sync(0xffffffffu, part[j], 1);
                part[j] += __shfl_xor_sync(0xffffffffu, part[j], 2);
            }
            if (tig == 0) {
#pragma unroll
                for (int j = 0; j < 9; j++)
                    atomicAdd(&red[rowL * 9 + j], part[j]);
            }
        }
    }
    __syncthreads();
    if (tid < 64) {
        float inv = 1.0f / red[tid * 9];
        float* o = out + (size_t)(bm + tid) * (NE * NQ) + e * NQ;
#pragma unroll
        for (int q = 0; q < 8; q++) o[q] = red[tid * 9 + 1 + q] * inv;
    }
}

// ---------------------------------------------------------------------------
extern "C" void kernel_launch(void* const* d_in, const int* in_sizes, int n_in,
                              void* d_out, int out_size)
{
    const float* x  = (const float*)d_in[0];
    const float* pw = (const float*)d_in[1];
    const float* qw = (const float*)d_in[2];
    float* out = (float*)d_out;

    cudaFuncSetAttribute(gemm_mma, cudaFuncAttributeMaxDynamicSharedMemorySize, K2_SMEM);
    cudaFuncSetAttribute(qsim_mma, cudaFuncAttributeMaxDynamicSharedMemorySize, K3_SMEM);

    gate_prep<<<1, 256>>>(qw);
    split_x<<<(NB * ND / 4 + 255) / 256, 256>>>(x);
    split_w<<<(NWIDE * ND / 4 + 255) / 256, 256>>>(pw);
    build_unitaries_reg<<<dim3(32, NE), 256>>>();
    gemm_mma<<<dim3(NWIDE / 128, NB / 128), 256, K2_SMEM>>>();
    qsim_mma<<<dim3(NB / 64, NE), 256, K3_SMEM>>>(out);
}

// round 6
// speedup vs baseline: 2.7049x; 1.0058x over previous
#include <cuda_runtime.h>
#include <cuda_bf16.h>
#include <math.h>
#include <stdint.h>

#define NQ 8
#define NL 2
#define NE 16
#define NS 256
#define NB 2048
#define ND 512
#define NWIDE (NE*NS)   // 4096

// ---------------- scratch (static device globals) ----------------
__device__ __nv_bfloat16 g_xh[(size_t)NB * ND];
__device__ __nv_bfloat16 g_xl[(size_t)NB * ND];
__device__ __nv_bfloat16 g_wh[(size_t)NWIDE * ND];
__device__ __nv_bfloat16 g_wl[(size_t)NWIDE * ND];
__device__ __nv_bfloat16 g_ah[(size_t)NB * NWIDE];
__device__ __nv_bfloat16 g_al[(size_t)NB * NWIDE];
__device__ __nv_bfloat16 g_urh[NE * NS * NS];   // [e][s][o]
__device__ __nv_bfloat16 g_url[NE * NS * NS];
__device__ __nv_bfloat16 g_uih[NE * NS * NS];
__device__ __nv_bfloat16 g_uil[NE * NS * NS];
__device__ float g_gates[NE * NL * NQ * 8];

// ---------------- mma.sync m16n8k16 bf16 ----------------
__device__ __forceinline__ void mma_bf16(float* d, const uint32_t* a, const uint32_t* b) {
    asm volatile(
        "mma.sync.aligned.m16n8k16.row.col.f32.bf16.bf16.f32 "
        "{%0,%1,%2,%3}, {%4,%5,%6,%7}, {%8,%9}, {%0,%1,%2,%3};"
        : "+f"(d[0]), "+f"(d[1]), "+f"(d[2]), "+f"(d[3])
        : "r"(a[0]), "r"(a[1]), "r"(a[2]), "r"(a[3]), "r"(b[0]), "r"(b[1]));
}

#define CP16(dst, src) \
    asm volatile("cp.async.cg.shared.global [%0], [%1], 16;" :: "r"(dst), "l"(src))
#define CP_COMMIT() asm volatile("cp.async.commit_group;")
#define CP_WAIT2()  asm volatile("cp.async.wait_group 2;")
#define CP_WAIT1()  asm volatile("cp.async.wait_group 1;")
#define CP_WAIT0()  asm volatile("cp.async.wait_group 0;")

#define PITCHB 144   // K2 smem row pitch bytes (64 bf16 + pad)
#define P3 80        // K3 smem row pitch bytes (32 bf16 + pad)

// ---------------------------------------------------------------------------
// Kernel 0 (merged): split x, split w, gate prep
// ---------------------------------------------------------------------------
__device__ __forceinline__ void split4(const float* __restrict__ src,
                                       __nv_bfloat16* hi, __nv_bfloat16* lo, int i)
{
    float4 v = ((const float4*)src)[i];
    __nv_bfloat16 h0 = __float2bfloat16_rn(v.x), h1 = __float2bfloat16_rn(v.y);
    __nv_bfloat16 h2 = __float2bfloat16_rn(v.z), h3 = __float2bfloat16_rn(v.w);
    __nv_bfloat162* hp = (__nv_bfloat162*)hi;
    __nv_bfloat162* lp = (__nv_bfloat162*)lo;
    hp[2*i]   = __nv_bfloat162(h0, h1);
    hp[2*i+1] = __nv_bfloat162(h2, h3);
    lp[2*i]   = __nv_bfloat162(__float2bfloat16_rn(v.x - __bfloat162float(h0)),
                               __float2bfloat16_rn(v.y - __bfloat162float(h1)));
    lp[2*i+1] = __nv_bfloat162(__float2bfloat16_rn(v.z - __bfloat162float(h2)),
                               __float2bfloat16_rn(v.w - __bfloat162float(h3)));
}

__global__ void __launch_bounds__(256) prep(const float* __restrict__ x,
                                            const float* __restrict__ pw,
                                            const float* __restrict__ qw)
{
    int bid = blockIdx.x;
    if (bid < 1024) {                       // x split: 1024*256 = NB*ND/4
        split4(x, g_xh, g_xl, bid * 256 + threadIdx.x);
    } else if (bid < 3072) {                // w split: 2048*256 = NWIDE*ND/4
        split4(pw, g_wh, g_wl, (bid - 1024) * 256 + threadIdx.x);
    } else {                                // gate matrices
        int g = threadIdx.x;
        if (g < NE * NL * NQ) {
            const float* w = qw + g * 3;
            float phi = w[0], th = w[1], om = w[2];
            float s_, c_, sa, ca, sm2, cm2;
            sincosf(0.5f * th, &s_, &c_);
            sincosf(0.5f * (phi + om), &sa, &ca);
            sincosf(0.5f * (phi - om), &sm2, &cm2);
            float* o = g_gates + g * 8;
            o[0] =  ca * c_;  o[1] = -sa * c_;
            o[2] = -cm2 * s_; o[3] = -sm2 * s_;
            o[4] =  cm2 * s_; o[5] = -sm2 * s_;
            o[6] =  ca * c_;  o[7] =  sa * c_;
        }
    }
}

// ---------------------------------------------------------------------------
// Kernel 1: register-resident statevector simulator (known-good)
// ---------------------------------------------------------------------------
__global__ void __launch_bounds__(256) build_unitaries_reg()
{
    const int e    = blockIdx.y;
    const int w    = threadIdx.x >> 5;
    const int c    = blockIdx.x * 8 + w;
    const int lane = threadIdx.x & 31;

    float ar[8], ai[8];
#pragma unroll
    for (int j = 0; j < 8; j++) {
        ar[j] = (((j << 5) | lane) == c) ? 1.f : 0.f;
        ai[j] = 0.f;
    }

#pragma unroll
    for (int l = 0; l < NL; l++) {
#pragma unroll
        for (int q = 0; q < NQ; q++) {
            const float4* gp = (const float4*)&g_gates[(((e * NL) + l) * NQ + q) * 8];
            float4 gA = gp[0], gB = gp[1];
            const float g00r = gA.x, g00i = gA.y, g01r = gA.z, g01i = gA.w;
            const float g10r = gB.x, g10i = gB.y, g11r = gB.z, g11i = gB.w;
            const int m = 1 << (7 - q);
            if (m >= 32) {
                const int jm = m >> 5;
#pragma unroll
                for (int j = 0; j < 8; j++) if (!(j & jm)) {
                    int j2 = j | jm;
                    float u0r = ar[j], u0i = ai[j], u1r = ar[j2], u1i = ai[j2];
                    ar[j]  = g00r*u0r - g00i*u0i + g01r*u1r - g01i*u1i;
                    ai[j]  = g00r*u0i + g00i*u0r + g01r*u1i + g01i*u1r;
                    ar[j2] = g10r*u0r - g10i*u0i + g11r*u1r - g11i*u1i;
                    ai[j2] = g10r*u0i + g10i*u0r + g11r*u1i + g11i*u1r;
                }
            } else {
                const bool hib = (lane & m) != 0;
                const float c0r = hib ? g10r : g00r, c0i = hib ? g10i : g00i;
                const float c1r = hib ? g11r : g01r, c1i = hib ? g11i : g01i;
#pragma unroll
                for (int j = 0; j < 8; j++) {
                    float br = __shfl_xor_sync(0xffffffffu, ar[j], m);
                    float bi = __shfl_xor_sync(0xffffffffu, ai[j], m);
                    float u0r = hib ? br : ar[j], u0i = hib ? bi : ai[j];
                    float u1r = hib ? ar[j] : br, u1i = hib ? ai[j] : bi;
                    ar[j] = c0r*u0r - c0i*u0i + c1r*u1r - c1i*u1i;
                    ai[j] = c0r*u0i + c0i*u0r + c1r*u1i + c1i*u1r;
                }
            }
        }
        const int r = (l % (NQ - 1)) + 1;
#pragma unroll
        for (int q = 0; q < NQ; q++) {
            const int cm = 1 << (7 - q);
            const int tm = 1 << (7 - ((q + r) % NQ));
            if (tm >= 32) {
                const int jt = tm >> 5;
#pragma unroll
                for (int j = 0; j < 8; j++) if (!(j & jt)) {
                    int j2 = j | jt;
                    bool cond = ((((j << 5) | lane) & cm) != 0);
                    float t0 = ar[j], t1 = ar[j2];
                    ar[j] = cond ? t1 : t0; ar[j2] = cond ? t0 : t1;
                    t0 = ai[j]; t1 = ai[j2];
                    ai[j] = cond ? t1 : t0; ai[j2] = cond ? t0 : t1;
                }
            } else {
#pragma unroll
                for (int j = 0; j < 8; j++) {
                    float br = __shfl_xor_sync(0xffffffffu, ar[j], tm);
                    float bi = __shfl_xor_sync(0xffffffffu, ai[j], tm);
                    bool cond = ((((j << 5) | lane) & cm) != 0);
                    ar[j] = cond ? br : ar[j];
                    ai[j] = cond ? bi : ai[j];
                }
            }
        }
    }

    __shared__ __nv_bfloat16 st[4][NS][8];
#pragma unroll
    for (int j = 0; j < 8; j++) {
        int s = (j << 5) | lane;
        __nv_bfloat16 hr = __float2bfloat16_rn(ar[j]);
        __nv_bfloat16 hi = __float2bfloat16_rn(ai[j]);
        st[0][s][w] = hr;
        st[1][s][w] = __float2bfloat16_rn(ar[j] - __bfloat162float(hr));
        st[2][s][w] = hi;
        st[3][s][w] = __float2bfloat16_rn(ai[j] - __bfloat162float(hi));
    }
    __syncthreads();
    const int s = threadIdx.x;
    size_t idx = ((size_t)(e * NS) + s) * NS + blockIdx.x * 8;
    *(uint4*)(g_urh + idx) = *(const uint4*)&st[0][s][0];
    *(uint4*)(g_url + idx) = *(const uint4*)&st[1][s][0];
    *(uint4*)(g_uih + idx) = *(const uint4*)&st[2][s][0];
    *(uint4*)(g_uil + idx) = *(const uint4*)&st[3][s][0];
}

// ---------------------------------------------------------------------------
// Kernel 2: projection GEMM, 3-stage cp.async, product-pass-outer MMA order.
// ---------------------------------------------------------------------------
#define K2_AH 0
#define K2_AL (128*PITCHB)
#define K2_BH (2*128*PITCHB)
#define K2_BL (3*128*PITCHB)
#define K2_STG (4*128*PITCHB)     // 73728
#define K2_SMEM (3*K2_STG)        // 221184

__global__ void __launch_bounds__(256) gemm_mma()
{
    extern __shared__ char sm[];
    const uint32_t smu = (uint32_t)__cvta_generic_to_shared(sm);
    const int tid  = threadIdx.x;
    const int lane = tid & 31, wid = tid >> 5;
    const int gid  = lane >> 2, tig = lane & 3;
    const int wm   = wid & 3,  wn  = wid >> 2;
    const int bm   = blockIdx.y * 128, bn = blockIdx.x * 128;

    float acc[2][8][4];
#pragma unroll
    for (int mt = 0; mt < 2; mt++)
#pragma unroll
        for (int nt = 0; nt < 8; nt++)
#pragma unroll
            for (int j = 0; j < 4; j++) acc[mt][nt][j] = 0.f;

    auto issue = [&](int ch) {
        const int k0 = ch * 64;
        const uint32_t sb = smu + (ch % 3) * K2_STG;
#pragma unroll
        for (int it = 0; it < 4; it++) {
            int i = tid + it * 256;
            int row = i >> 3, cc = i & 7;
            uint32_t d = row * PITCHB + cc * 16;
            size_t ga = (size_t)(bm + row) * ND + k0 + cc * 8;
            size_t gb = (size_t)(bn + row) * ND + k0 + cc * 8;
            CP16(sb + K2_AH + d, g_xh + ga);
            CP16(sb + K2_AL + d, g_xl + ga);
            CP16(sb + K2_BH + d, g_wh + gb);
            CP16(sb + K2_BL + d, g_wl + gb);
        }
        CP_COMMIT();
    };

    issue(0); issue(1);
    for (int ch = 0; ch < 8; ch++) {
        if (ch + 2 < 8) { issue(ch + 2); CP_WAIT2(); }
        else if (ch == 6) { CP_WAIT1(); }
        else              { CP_WAIT0(); }
        __syncthreads();
        const char* bp = sm + (ch % 3) * K2_STG;
#pragma unroll
        for (int kc = 0; kc < 4; kc++) {
            const int kb = kc * 32 + tig * 4;
            uint32_t ah[2][4], al[2][4];
#pragma unroll
            for (int mt = 0; mt < 2; mt++) {
                const char* base = bp + (wm * 32 + mt * 16 + gid) * PITCHB + kb;
                ah[mt][0] = *(const uint32_t*)(base + K2_AH);
                ah[mt][1] = *(const uint32_t*)(base + K2_AH + 8 * PITCHB);
                ah[mt][2] = *(const uint32_t*)(base + K2_AH + 16);
                ah[mt][3] = *(const uint32_t*)(base + K2_AH + 8 * PITCHB + 16);
                al[mt][0] = *(const uint32_t*)(base + K2_AL);
                al[mt][1] = *(const uint32_t*)(base + K2_AL + 8 * PITCHB);
                al[mt][2] = *(const uint32_t*)(base + K2_AL + 16);
                al[mt][3] = *(const uint32_t*)(base + K2_AL + 8 * PITCHB + 16);
            }
            uint32_t bh[8][2], bl[8][2];
#pragma unroll
            for (int nt = 0; nt < 8; nt++) {
                const char* base = bp + (wn * 64 + nt * 8 + gid) * PITCHB + kb;
                bh[nt][0] = *(const uint32_t*)(base + K2_BH);
                bh[nt][1] = *(const uint32_t*)(base + K2_BH + 16);
                bl[nt][0] = *(const uint32_t*)(base + K2_BL);
                bl[nt][1] = *(const uint32_t*)(base + K2_BL + 16);
            }
            // product-pass outer: same-acc reuse distance = 16 MMAs
#pragma unroll
            for (int nt = 0; nt < 8; nt++)
#pragma unroll
                for (int mt = 0; mt < 2; mt++) mma_bf16(acc[mt][nt], ah[mt], bh[nt]);
#pragma unroll
            for (int nt = 0; nt < 8; nt++)
#pragma unroll
                for (int mt = 0; mt < 2; mt++) mma_bf16(acc[mt][nt], ah[mt], bl[nt]);
#pragma unroll
            for (int nt = 0; nt < 8; nt++)
#pragma unroll
                for (int mt = 0; mt < 2; mt++) mma_bf16(acc[mt][nt], al[mt], bh[nt]);
        }
        __syncthreads();
    }

#pragma unroll
    for (int mt = 0; mt < 2; mt++) {
#pragma unroll
        for (int nt = 0; nt < 8; nt++) {
            int r0 = bm + wm * 32 + mt * 16 + gid;
            int n  = bn + wn * 64 + nt * 8 + 2 * tig;
            float v00 = acc[mt][nt][0], v01 = acc[mt][nt][1];
            float v10 = acc[mt][nt][2], v11 = acc[mt][nt][3];
            __nv_bfloat16 h00 = __float2bfloat16_rn(v00), h01 = __float2bfloat16_rn(v01);
            __nv_bfloat16 h10 = __float2bfloat16_rn(v10), h11 = __float2bfloat16_rn(v11);
            *(__nv_bfloat162*)(g_ah + (size_t)r0 * NWIDE + n) = __nv_bfloat162(h00, h01);
            *(__nv_bfloat162*)(g_al + (size_t)r0 * NWIDE + n) =
                __nv_bfloat162(__float2bfloat16_rn(v00 - __bfloat162float(h00)),
                               __float2bfloat16_rn(v01 - __bfloat162float(h01)));
            *(__nv_bfloat162*)(g_ah + (size_t)(r0 + 8) * NWIDE + n) = __nv_bfloat162(h10, h11);
            *(__nv_bfloat162*)(g_al + (size_t)(r0 + 8) * NWIDE + n) =
                __nv_bfloat162(__float2bfloat16_rn(v10 - __bfloat162float(h10)),
                               __float2bfloat16_rn(v11 - __bfloat162float(h11)));
        }
    }
}

// ---------------------------------------------------------------------------
// Kernel 3: complex GEMM + fused reduction; 2-stage; pass-outer MMA order
// with nt-halves to bound register pressure.
// ---------------------------------------------------------------------------
#define K3_AH 0
#define K3_AL  (64*P3)
#define K3_URH (2*64*P3)
#define K3_URL (K3_URH + 256*P3)
#define K3_UIH (K3_URL + 256*P3)
#define K3_UIL (K3_UIH + 256*P3)
#define K3_STG (K3_UIL + 256*P3)      // 92160
#define K3_SMEM (2*K3_STG + 64*9*4)   // 186624

__global__ void __launch_bounds__(256) qsim_mma(float* __restrict__ out)
{
    extern __shared__ char sm[];
    const uint32_t smu = (uint32_t)__cvta_generic_to_shared(sm);
    const int tid  = threadIdx.x;
    const int lane = tid & 31, wid = tid >> 5;
    const int gid  = lane >> 2, tig = lane & 3;
    const int wm   = wid & 1,  wn  = wid >> 1;
    const int e    = blockIdx.y;
    const int bm   = blockIdx.x * 64;

    float* red = (float*)(sm + 2 * K3_STG);
    for (int i = tid; i < 64 * 9; i += 256) red[i] = 0.f;

    float accR[2][8][4], accI[2][8][4];
#pragma unroll
    for (int mt = 0; mt < 2; mt++)
#pragma unroll
        for (int nt = 0; nt < 8; nt++)
#pragma unroll
            for (int j = 0; j < 4; j++) { accR[mt][nt][j] = 0.f; accI[mt][nt][j] = 0.f; }

    auto issue = [&](int ch, int p) {
        const int k0 = ch * 32;
        const uint32_t sb = smu + p * K3_STG;
        {
            int row = tid >> 2, cc = tid & 3;
            uint32_t d = row * P3 + cc * 16;
            size_t ga = (size_t)(bm + row) * NWIDE + e * NS + k0 + cc * 8;
            CP16(sb + K3_AH + d, g_ah + ga);
            CP16(sb + K3_AL + d, g_al + ga);
        }
#pragma unroll
        for (int it = 0; it < 4; it++) {
            int i = tid + it * 256;
            int row = i >> 2, cc = i & 3;
            uint32_t d = row * P3 + cc * 16;
            size_t gu = ((size_t)(e * NS) + row) * NS + k0 + cc * 8;
            CP16(sb + K3_URH + d, g_urh + gu);
            CP16(sb + K3_URL + d, g_url + gu);
            CP16(sb + K3_UIH + d, g_uih + gu);
            CP16(sb + K3_UIL + d, g_uil + gu);
        }
        CP_COMMIT();
    };

    issue(0, 0);
    for (int ch = 0; ch < 8; ch++) {
        if (ch + 1 < 8) { issue(ch + 1, (ch + 1) & 1); CP_WAIT1(); }
        else            { CP_WAIT0(); }
        __syncthreads();
        const char* bp = sm + (ch & 1) * K3_STG;
#pragma unroll
        for (int kc = 0; kc < 2; kc++) {
            const int kb = kc * 32 + tig * 4;
            uint32_t ah[2][4], al[2][4];
#pragma unroll
            for (int mt = 0; mt < 2; mt++) {
                const char* base = bp + (wm * 32 + mt * 16 + gid) * P3 + kb;
                ah[mt][0] = *(const uint32_t*)(base + K3_AH);
                ah[mt][1] = *(const uint32_t*)(base + K3_AH + 8 * P3);
                ah[mt][2] = *(const uint32_t*)(base + K3_AH + 16);
                ah[mt][3] = *(const uint32_t*)(base + K3_AH + 8 * P3 + 16);
                al[mt][0] = *(const uint32_t*)(base + K3_AL);
                al[mt][1] = *(const uint32_t*)(base + K3_AL + 8 * P3);
                al[mt][2] = *(const uint32_t*)(base + K3_AL + 16);
                al[mt][3] = *(const uint32_t*)(base + K3_AL + 8 * P3 + 16);
            }
#pragma unroll
            for (int h = 0; h < 2; h++) {
                uint32_t urh[4][2], url[4][2], uih[4][2], uil[4][2];
#pragma unroll
                for (int n4 = 0; n4 < 4; n4++) {
                    int nt = h * 4 + n4;
                    const char* base = bp + (wn * 64 + nt * 8 + gid) * P3 + kb;
                    urh[n4][0] = *(const uint32_t*)(base + K3_URH);
                    urh[n4][1] = *(const uint32_t*)(base + K3_URH + 16);
                    url[n4][0] = *(const uint32_t*)(base + K3_URL);
                    url[n4][1] = *(const uint32_t*)(base + K3_URL + 16);
                    uih[n4][0] = *(const uint32_t*)(base + K3_UIH);
                    uih[n4][1] = *(const uint32_t*)(base + K3_UIH + 16);
                    uil[n4][0] = *(const uint32_t*)(base + K3_UIL);
                    uil[n4][1] = *(const uint32_t*)(base + K3_UIL + 16);
                }
                // pass-outer: same-acc reuse distance = 16 MMAs
#pragma unroll
                for (int n4 = 0; n4 < 4; n4++)
#pragma unroll
                    for (int mt = 0; mt < 2; mt++) mma_bf16(accR[mt][h*4+n4], ah[mt], urh[n4]);
#pragma unroll
                for (int n4 = 0; n4 < 4; n4++)
#pragma unroll
                    for (int mt = 0; mt < 2; mt++) mma_bf16(accI[mt][h*4+n4], ah[mt], uih[n4]);
#pragma unroll
                for (int n4 = 0; n4 < 4; n4++)
#pragma unroll
                    for (int mt = 0; mt < 2; mt++) mma_bf16(accR[mt][h*4+n4], ah[mt], url[n4]);
#pragma unroll
                for (int n4 = 0; n4 < 4; n4++)
#pragma unroll
                    for (int mt = 0; mt < 2; mt++) mma_bf16(accI[mt][h*4+n4], ah[mt], uil[n4]);
#pragma unroll
                for (int n4 = 0; n4 < 4; n4++)
#pragma unroll
                    for (int mt = 0; mt < 2; mt++) mma_bf16(accR[mt][h*4+n4], al[mt], urh[n4]);
#pragma unroll
                for (int n4 = 0; n4 < 4; n4++)
#pragma unroll
                    for (int mt = 0; mt < 2; mt++) mma_bf16(accI[mt][h*4+n4], al[mt], uih[n4]);
            }
        }
        __syncthreads();
    }

    // fused epilogue: p = |y|^2; tot + 8 signed sums; normalize
#pragma unroll
    for (int mt = 0; mt < 2; mt++) {
#pragma unroll
        for (int half = 0; half < 2; half++) {
            int rowL = wm * 32 + mt * 16 + gid + half * 8;
            float part[9];
#pragma unroll
            for (int j = 0; j < 9; j++) part[j] = 0.f;
#pragma unroll
            for (int nt = 0; nt < 8; nt++) {
#pragma unroll
                for (int j = 0; j < 2; j++) {
                    float vr = accR[mt][nt][half * 2 + j];
                    float vi = accI[mt][nt][half * 2 + j];
                    float p = vr * vr + vi * vi;
                    int s = wn * 64 + nt * 8 + 2 * tig + j;
                    part[0] += p;
#pragma unroll
                    for (int q = 0; q < 8; q++)
                        part[1 + q] += ((s >> (7 - q)) & 1) ? -p : p;
                }
            }
#pragma unroll
            for (int j = 0; j < 9; j++) {
                part[j] += __shfl_xor_sync(0xffffffffu, part[j], 1);
                part[j] += __shfl_xor_sync(0xffffffffu, part[j], 2);
            }
            if (tig == 0) {
#pragma unroll
                for (int j = 0; j < 9; j++)
                    atomicAdd(&red[rowL * 9 + j], part[j]);
            }
        }
    }
    __syncthreads();
    if (tid < 64) {
        float inv = 1.0f / red[tid * 9];
        float* o = out + (size_t)(bm + tid) * (NE * NQ) + e * NQ;
#pragma unroll
        for (int q = 0; q < 8; q++) o[q] = red[tid * 9 + 1 + q] * inv;
    }
}

// ---------------------------------------------------------------------------
extern "C" void kernel_launch(void* const* d_in, const int* in_sizes, int n_in,
                              void* d_out, int out_size)
{
    const float* x  = (const float*)d_in[0];
    const float* pw = (const float*)d_in[1];
    const float* qw = (const float*)d_in[2];
    float* out = (float*)d_out;

    cudaFuncSetAttribute(gemm_mma, cudaFuncAttributeMaxDynamicSharedMemorySize, K2_SMEM);
    cudaFuncSetAttribute(qsim_mma, cudaFuncAttributeMaxDynamicSharedMemorySize, K3_SMEM);

    prep<<<3073, 256>>>(x, pw, qw);
    build_unitaries_reg<<<dim3(32, NE), 256>>>();
    gemm_mma<<<dim3(NWIDE / 128, NB / 128), 256, K2_SMEM>>>();
    qsim_mma<<<dim3(NB / 64, NE), 256, K3_SMEM>>>(out);
}

// round 7
// speedup vs baseline: 2.9838x; 1.1031x over previous
#include <cuda_runtime.h>
#include <cuda_bf16.h>
#include <math.h>
#include <stdint.h>

#define NQ 8
#define NL 2
#define NE 16
#define NS 256
#define NB 2048
#define ND 512
#define NWIDE (NE*NS)   // 4096

// ---------------- scratch (static device globals) ----------------
__device__ __nv_bfloat16 g_xh[(size_t)NB * ND];
__device__ __nv_bfloat16 g_xl[(size_t)NB * ND];
__device__ __nv_bfloat16 g_wh[(size_t)NWIDE * ND];
__device__ __nv_bfloat16 g_wl[(size_t)NWIDE * ND];
__device__ __nv_bfloat16 g_ah[(size_t)NB * NWIDE];
__device__ __nv_bfloat16 g_al[(size_t)NB * NWIDE];
__device__ __nv_bfloat16 g_urh[NE * NS * NS];   // [e][s][o]
__device__ __nv_bfloat16 g_url[NE * NS * NS];
__device__ __nv_bfloat16 g_uih[NE * NS * NS];
__device__ __nv_bfloat16 g_uil[NE * NS * NS];
__device__ float g_gates[NE * NL * NQ * 8];
__device__ float g_part[(size_t)32 * NB * 9];   // [e*2+half][b][9]

// ---------------- mma.sync m16n8k16 bf16 ----------------
__device__ __forceinline__ void mma_bf16(float* d, const uint32_t* a, const uint32_t* b) {
    asm volatile(
        "mma.sync.aligned.m16n8k16.row.col.f32.bf16.bf16.f32 "
        "{%0,%1,%2,%3}, {%4,%5,%6,%7}, {%8,%9}, {%0,%1,%2,%3};"
        : "+f"(d[0]), "+f"(d[1]), "+f"(d[2]), "+f"(d[3])
        : "r"(a[0]), "r"(a[1]), "r"(a[2]), "r"(a[3]), "r"(b[0]), "r"(b[1]));
}

#define CP16(dst, src) \
    asm volatile("cp.async.cg.shared.global [%0], [%1], 16;" :: "r"(dst), "l"(src))
#define CP_COMMIT() asm volatile("cp.async.commit_group;")
#define CP_WAIT1()  asm volatile("cp.async.wait_group 1;")
#define CP_WAIT0()  asm volatile("cp.async.wait_group 0;")

#define PCH 80   // smem row pitch bytes (32 bf16 + 16B pad)

// ---------------------------------------------------------------------------
// Kernel 0 (merged): split x, split w, gate prep
// ---------------------------------------------------------------------------
__device__ __forceinline__ void split4(const float* __restrict__ src,
                                       __nv_bfloat16* hi, __nv_bfloat16* lo, int i)
{
    float4 v = ((const float4*)src)[i];
    __nv_bfloat16 h0 = __float2bfloat16_rn(v.x), h1 = __float2bfloat16_rn(v.y);
    __nv_bfloat16 h2 = __float2bfloat16_rn(v.z), h3 = __float2bfloat16_rn(v.w);
    __nv_bfloat162* hp = (__nv_bfloat162*)hi;
    __nv_bfloat162* lp = (__nv_bfloat162*)lo;
    hp[2*i]   = __nv_bfloat162(h0, h1);
    hp[2*i+1] = __nv_bfloat162(h2, h3);
    lp[2*i]   = __nv_bfloat162(__float2bfloat16_rn(v.x - __bfloat162float(h0)),
                               __float2bfloat16_rn(v.y - __bfloat162float(h1)));
    lp[2*i+1] = __nv_bfloat162(__float2bfloat16_rn(v.z - __bfloat162float(h2)),
                               __float2bfloat16_rn(v.w - __bfloat162float(h3)));
}

__global__ void __launch_bounds__(256) prep(const float* __restrict__ x,
                                            const float* __restrict__ pw,
                                            const float* __restrict__ qw)
{
    int bid = blockIdx.x;
    if (bid < 1024) {
        split4(x, g_xh, g_xl, bid * 256 + threadIdx.x);
    } else if (bid < 3072) {
        split4(pw, g_wh, g_wl, (bid - 1024) * 256 + threadIdx.x);
    } else {
        int g = threadIdx.x;
        if (g < NE * NL * NQ) {
            const float* w = qw + g * 3;
            float phi = w[0], th = w[1], om = w[2];
            float s_, c_, sa, ca, sm2, cm2;
            sincosf(0.5f * th, &s_, &c_);
            sincosf(0.5f * (phi + om), &sa, &ca);
            sincosf(0.5f * (phi - om), &sm2, &cm2);
            float* o = g_gates + g * 8;
            o[0] =  ca * c_;  o[1] = -sa * c_;
            o[2] = -cm2 * s_; o[3] = -sm2 * s_;
            o[4] =  cm2 * s_; o[5] = -sm2 * s_;
            o[6] =  ca * c_;  o[7] =  sa * c_;
        }
    }
}

// ---------------------------------------------------------------------------
// Kernel 1: register-resident statevector simulator (known-good)
// ---------------------------------------------------------------------------
__global__ void __launch_bounds__(256) build_unitaries_reg()
{
    const int e    = blockIdx.y;
    const int w    = threadIdx.x >> 5;
    const int c    = blockIdx.x * 8 + w;
    const int lane = threadIdx.x & 31;

    float ar[8], ai[8];
#pragma unroll
    for (int j = 0; j < 8; j++) {
        ar[j] = (((j << 5) | lane) == c) ? 1.f : 0.f;
        ai[j] = 0.f;
    }

#pragma unroll
    for (int l = 0; l < NL; l++) {
#pragma unroll
        for (int q = 0; q < NQ; q++) {
            const float4* gp = (const float4*)&g_gates[(((e * NL) + l) * NQ + q) * 8];
            float4 gA = gp[0], gB = gp[1];
            const float g00r = gA.x, g00i = gA.y, g01r = gA.z, g01i = gA.w;
            const float g10r = gB.x, g10i = gB.y, g11r = gB.z, g11i = gB.w;
            const int m = 1 << (7 - q);
            if (m >= 32) {
                const int jm = m >> 5;
#pragma unroll
                for (int j = 0; j < 8; j++) if (!(j & jm)) {
                    int j2 = j | jm;
                    float u0r = ar[j], u0i = ai[j], u1r = ar[j2], u1i = ai[j2];
                    ar[j]  = g00r*u0r - g00i*u0i + g01r*u1r - g01i*u1i;
                    ai[j]  = g00r*u0i + g00i*u0r + g01r*u1i + g01i*u1r;
                    ar[j2] = g10r*u0r - g10i*u0i + g11r*u1r - g11i*u1i;
                    ai[j2] = g10r*u0i + g10i*u0r + g11r*u1i + g11i*u1r;
                }
            } else {
                const bool hib = (lane & m) != 0;
                const float c0r = hib ? g10r : g00r, c0i = hib ? g10i : g00i;
                const float c1r = hib ? g11r : g01r, c1i = hib ? g11i : g01i;
#pragma unroll
                for (int j = 0; j < 8; j++) {
                    float br = __shfl_xor_sync(0xffffffffu, ar[j], m);
                    float bi = __shfl_xor_sync(0xffffffffu, ai[j], m);
                    float u0r = hib ? br : ar[j], u0i = hib ? bi : ai[j];
                    float u1r = hib ? ar[j] : br, u1i = hib ? ai[j] : bi;
                    ar[j] = c0r*u0r - c0i*u0i + c1r*u1r - c1i*u1i;
                    ai[j] = c0r*u0i + c0i*u0r + c1r*u1i + c1i*u1r;
                }
            }
        }
        const int r = (l % (NQ - 1)) + 1;
#pragma unroll
        for (int q = 0; q < NQ; q++) {
            const int cm = 1 << (7 - q);
            const int tm = 1 << (7 - ((q + r) % NQ));
            if (tm >= 32) {
                const int jt = tm >> 5;
#pragma unroll
                for (int j = 0; j < 8; j++) if (!(j & jt)) {
                    int j2 = j | jt;
                    bool cond = ((((j << 5) | lane) & cm) != 0);
                    float t0 = ar[j], t1 = ar[j2];
                    ar[j] = cond ? t1 : t0; ar[j2] = cond ? t0 : t1;
                    t0 = ai[j]; t1 = ai[j2];
                    ai[j] = cond ? t1 : t0; ai[j2] = cond ? t0 : t1;
                }
            } else {
#pragma unroll
                for (int j = 0; j < 8; j++) {
                    float br = __shfl_xor_sync(0xffffffffu, ar[j], tm);
                    float bi = __shfl_xor_sync(0xffffffffu, ai[j], tm);
                    bool cond = ((((j << 5) | lane) & cm) != 0);
                    ar[j] = cond ? br : ar[j];
                    ai[j] = cond ? bi : ai[j];
                }
            }
        }
    }

    __shared__ __nv_bfloat16 st[4][NS][8];
#pragma unroll
    for (int j = 0; j < 8; j++) {
        int s = (j << 5) | lane;
        __nv_bfloat16 hr = __float2bfloat16_rn(ar[j]);
        __nv_bfloat16 hi = __float2bfloat16_rn(ai[j]);
        st[0][s][w] = hr;
        st[1][s][w] = __float2bfloat16_rn(ar[j] - __bfloat162float(hr));
        st[2][s][w] = hi;
        st[3][s][w] = __float2bfloat16_rn(ai[j] - __bfloat162float(hi));
    }
    __syncthreads();
    const int s = threadIdx.x;
    size_t idx = ((size_t)(e * NS) + s) * NS + blockIdx.x * 8;
    *(uint4*)(g_urh + idx) = *(const uint4*)&st[0][s][0];
    *(uint4*)(g_url + idx) = *(const uint4*)&st[1][s][0];
    *(uint4*)(g_uih + idx) = *(const uint4*)&st[2][s][0];
    *(uint4*)(g_uil + idx) = *(const uint4*)&st[3][s][0];
}

// ---------------------------------------------------------------------------
// Kernel 2: projection GEMM. KC=32, 2 stages x 40KB -> 2 CTAs/SM.
// ---------------------------------------------------------------------------
#define K2_AH 0
#define K2_AL (128*PCH)        // 10240
#define K2_BH (2*128*PCH)      // 20480
#define K2_BL (3*128*PCH)      // 30720
#define K2_STG (4*128*PCH)     // 40960
#define K2_SMEM (2*K2_STG)     // 81920

__global__ void __launch_bounds__(256, 2) gemm_mma()
{
    extern __shared__ char sm[];
    const uint32_t smu = (uint32_t)__cvta_generic_to_shared(sm);
    const int tid  = threadIdx.x;
    const int lane = tid & 31, wid = tid >> 5;
    const int gid  = lane >> 2, tig = lane & 3;
    const int wm   = wid & 3,  wn  = wid >> 2;      // 4(M) x 2(N)
    const int bm   = blockIdx.y * 128, bn = blockIdx.x * 128;

    float acc[2][8][4];
#pragma unroll
    for (int mt = 0; mt < 2; mt++)
#pragma unroll
        for (int nt = 0; nt < 8; nt++)
#pragma unroll
            for (int j = 0; j < 4; j++) acc[mt][nt][j] = 0.f;

    auto issue = [&](int ch) {
        const int k0 = ch * 32;
        const uint32_t sb = smu + (ch & 1) * K2_STG;
#pragma unroll
        for (int it = 0; it < 2; it++) {
            int i = tid + it * 256;
            int row = i >> 2, cc = i & 3;
            uint32_t d = row * PCH + cc * 16;
            size_t ga = (size_t)(bm + row) * ND + k0 + cc * 8;
            size_t gb = (size_t)(bn + row) * ND + k0 + cc * 8;
            CP16(sb + K2_AH + d, g_xh + ga);
            CP16(sb + K2_AL + d, g_xl + ga);
            CP16(sb + K2_BH + d, g_wh + gb);
            CP16(sb + K2_BL + d, g_wl + gb);
        }
        CP_COMMIT();
    };

    issue(0);
    for (int ch = 0; ch < 16; ch++) {
        if (ch + 1 < 16) { issue(ch + 1); CP_WAIT1(); }
        else             { CP_WAIT0(); }
        __syncthreads();
        const char* bp = sm + (ch & 1) * K2_STG;
#pragma unroll
        for (int kc = 0; kc < 2; kc++) {
            const int kb = kc * 32 + tig * 4;
            uint32_t ah[2][4], al[2][4];
#pragma unroll
            for (int mt = 0; mt < 2; mt++) {
                const char* base = bp + (wm * 32 + mt * 16 + gid) * PCH + kb;
                ah[mt][0] = *(const uint32_t*)(base + K2_AH);
                ah[mt][1] = *(const uint32_t*)(base + K2_AH + 8 * PCH);
                ah[mt][2] = *(const uint32_t*)(base + K2_AH + 16);
                ah[mt][3] = *(const uint32_t*)(base + K2_AH + 8 * PCH + 16);
                al[mt][0] = *(const uint32_t*)(base + K2_AL);
                al[mt][1] = *(const uint32_t*)(base + K2_AL + 8 * PCH);
                al[mt][2] = *(const uint32_t*)(base + K2_AL + 16);
                al[mt][3] = *(const uint32_t*)(base + K2_AL + 8 * PCH + 16);
            }
#pragma unroll
            for (int hB = 0; hB < 2; hB++) {
                uint32_t bh[4][2], bl[4][2];
#pragma unroll
                for (int n4 = 0; n4 < 4; n4++) {
                    int nt = hB * 4 + n4;
                    const char* base = bp + (wn * 64 + nt * 8 + gid) * PCH + kb;
                    bh[n4][0] = *(const uint32_t*)(base + K2_BH);
                    bh[n4][1] = *(const uint32_t*)(base + K2_BH + 16);
                    bl[n4][0] = *(const uint32_t*)(base + K2_BL);
                    bl[n4][1] = *(const uint32_t*)(base + K2_BL + 16);
                }
#pragma unroll
                for (int n4 = 0; n4 < 4; n4++)
#pragma unroll
                    for (int mt = 0; mt < 2; mt++) mma_bf16(acc[mt][hB*4+n4], ah[mt], bh[n4]);
#pragma unroll
                for (int n4 = 0; n4 < 4; n4++)
#pragma unroll
                    for (int mt = 0; mt < 2; mt++) mma_bf16(acc[mt][hB*4+n4], ah[mt], bl[n4]);
#pragma unroll
                for (int n4 = 0; n4 < 4; n4++)
#pragma unroll
                    for (int mt = 0; mt < 2; mt++) mma_bf16(acc[mt][hB*4+n4], al[mt], bh[n4]);
            }
        }
        __syncthreads();
    }

#pragma unroll
    for (int mt = 0; mt < 2; mt++) {
#pragma unroll
        for (int nt = 0; nt < 8; nt++) {
            int r0 = bm + wm * 32 + mt * 16 + gid;
            int n  = bn + wn * 64 + nt * 8 + 2 * tig;
            float v00 = acc[mt][nt][0], v01 = acc[mt][nt][1];
            float v10 = acc[mt][nt][2], v11 = acc[mt][nt][3];
            __nv_bfloat16 h00 = __float2bfloat16_rn(v00), h01 = __float2bfloat16_rn(v01);
            __nv_bfloat16 h10 = __float2bfloat16_rn(v10), h11 = __float2bfloat16_rn(v11);
            *(__nv_bfloat162*)(g_ah + (size_t)r0 * NWIDE + n) = __nv_bfloat162(h00, h01);
            *(__nv_bfloat162*)(g_al + (size_t)r0 * NWIDE + n) =
                __nv_bfloat162(__float2bfloat16_rn(v00 - __bfloat162float(h00)),
                               __float2bfloat16_rn(v01 - __bfloat162float(h01)));
            *(__nv_bfloat162*)(g_ah + (size_t)(r0 + 8) * NWIDE + n) = __nv_bfloat162(h10, h11);
            *(__nv_bfloat162*)(g_al + (size_t)(r0 + 8) * NWIDE + n) =
                __nv_bfloat162(__float2bfloat16_rn(v10 - __bfloat162float(h10)),
                               __float2bfloat16_rn(v11 - __bfloat162float(h11)));
        }
    }
}

// ---------------------------------------------------------------------------
// Kernel 3: complex GEMM, N split in two 128-halves per CTA -> 2 CTAs/SM.
// Emits partial 9-sums to g_part; combine kernel normalizes.
// ---------------------------------------------------------------------------
#define K3_AH 0
#define K3_AL  (64*PCH)            // 5120
#define K3_URH (2*64*PCH)          // 10240
#define K3_URL (K3_URH + 128*PCH)  // 20480
#define K3_UIH (K3_URL + 128*PCH)  // 30720
#define K3_UIL (K3_UIH + 128*PCH)  // 40960
#define K3_STG (K3_UIL + 128*PCH)  // 51200
#define K3_SMEM (2*K3_STG + 64*9*4)  // 104704

__global__ void __launch_bounds__(256, 2) qsim_mma()
{
    extern __shared__ char sm[];
    const uint32_t smu = (uint32_t)__cvta_generic_to_shared(sm);
    const int tid  = threadIdx.x;
    const int lane = tid & 31, wid = tid >> 5;
    const int gid  = lane >> 2, tig = lane & 3;
    const int wm   = wid & 1,  wn  = wid >> 1;     // 2(M) x 4(N)
    const int e    = blockIdx.y >> 1;
    const int half = blockIdx.y & 1;
    const int bm   = blockIdx.x * 64;

    float* red = (float*)(sm + 2 * K3_STG);
    for (int i = tid; i < 64 * 9; i += 256) red[i] = 0.f;

    float accR[2][4][4], accI[2][4][4];
#pragma unroll
    for (int mt = 0; mt < 2; mt++)
#pragma unroll
        for (int nt = 0; nt < 4; nt++)
#pragma unroll
            for (int j = 0; j < 4; j++) { accR[mt][nt][j] = 0.f; accI[mt][nt][j] = 0.f; }

    auto issue = [&](int ch) {
        const int k0 = ch * 32;
        const uint32_t sb = smu + (ch & 1) * K3_STG;
        {
            int row = tid >> 2, cc = tid & 3;
            uint32_t d = row * PCH + cc * 16;
            size_t ga = (size_t)(bm + row) * NWIDE + e * NS + k0 + cc * 8;
            CP16(sb + K3_AH + d, g_ah + ga);
            CP16(sb + K3_AL + d, g_al + ga);
        }
#pragma unroll
        for (int it = 0; it < 2; it++) {
            int i = tid + it * 256;
            int row = i >> 2, cc = i & 3;
            uint32_t d = row * PCH + cc * 16;
            size_t gu = ((size_t)(e * NS) + half * 128 + row) * NS + k0 + cc * 8;
            CP16(sb + K3_URH + d, g_urh + gu);
            CP16(sb + K3_URL + d, g_url + gu);
            CP16(sb + K3_UIH + d, g_uih + gu);
            CP16(sb + K3_UIL + d, g_uil + gu);
        }
        CP_COMMIT();
    };

    issue(0);
    for (int ch = 0; ch < 8; ch++) {
        if (ch + 1 < 8) { issue(ch + 1); CP_WAIT1(); }
        else            { CP_WAIT0(); }
        __syncthreads();
        const char* bp = sm + (ch & 1) * K3_STG;
#pragma unroll
        for (int kc = 0; kc < 2; kc++) {
            const int kb = kc * 32 + tig * 4;
            uint32_t ah[2][4], al[2][4];
#pragma unroll
            for (int mt = 0; mt < 2; mt++) {
                const char* base = bp + (wm * 32 + mt * 16 + gid) * PCH + kb;
                ah[mt][0] = *(const uint32_t*)(base + K3_AH);
                ah[mt][1] = *(const uint32_t*)(base + K3_AH + 8 * PCH);
                ah[mt][2] = *(const uint32_t*)(base + K3_AH + 16);
                ah[mt][3] = *(const uint32_t*)(base + K3_AH + 8 * PCH + 16);
                al[mt][0] = *(const uint32_t*)(base + K3_AL);
                al[mt][1] = *(const uint32_t*)(base + K3_AL + 8 * PCH);
                al[mt][2] = *(const uint32_t*)(base + K3_AL + 16);
                al[mt][3] = *(const uint32_t*)(base + K3_AL + 8 * PCH + 16);
            }
            // real part
            {
                uint32_t uh[4][2], ul[4][2];
#pragma unroll
                for (int nt = 0; nt < 4; nt++) {
                    const char* base = bp + (wn * 32 + nt * 8 + gid) * PCH + kb;
                    uh[nt][0] = *(const uint32_t*)(base + K3_URH);
                    uh[nt][1] = *(const uint32_t*)(base + K3_URH + 16);
                    ul[nt][0] = *(const uint32_t*)(base + K3_URL);
                    ul[nt][1] = *(const uint32_t*)(base + K3_URL + 16);
                }
#pragma unroll
                for (int nt = 0; nt < 4; nt++)
#pragma unroll
                    for (int mt = 0; mt < 2; mt++) mma_bf16(accR[mt][nt], ah[mt], uh[nt]);
#pragma unroll
                for (int nt = 0; nt < 4; nt++)
#pragma unroll
                    for (int mt = 0; mt < 2; mt++) mma_bf16(accR[mt][nt], ah[mt], ul[nt]);
#pragma unroll
                for (int nt = 0; nt < 4; nt++)
#pragma unroll
                    for (int mt = 0; mt < 2; mt++) mma_bf16(accR[mt][nt], al[mt], uh[nt]);
            }
            // imag part
            {
                uint32_t uh[4][2], ul[4][2];
#pragma unroll
                for (int nt = 0; nt < 4; nt++) {
                    const char* base = bp + (wn * 32 + nt * 8 + gid) * PCH + kb;
                    uh[nt][0] = *(const uint32_t*)(base + K3_UIH);
                    uh[nt][1] = *(const uint32_t*)(base + K3_UIH + 16);
                    ul[nt][0] = *(const uint32_t*)(base + K3_UIL);
                    ul[nt][1] = *(const uint32_t*)(base + K3_UIL + 16);
                }
#pragma unroll
                for (int nt = 0; nt < 4; nt++)
#pragma unroll
                    for (int mt = 0; mt < 2; mt++) mma_bf16(accI[mt][nt], ah[mt], uh[nt]);
#pragma unroll
                for (int nt = 0; nt < 4; nt++)
#pragma unroll
                    for (int mt = 0; mt < 2; mt++) mma_bf16(accI[mt][nt], ah[mt], ul[nt]);
#pragma unroll
                for (int nt = 0; nt < 4; nt++)
#pragma unroll
                    for (int mt = 0; mt < 2; mt++) mma_bf16(accI[mt][nt], al[mt], uh[nt]);
            }
        }
        __syncthreads();
    }

    // partial epilogue: p = |y|^2; tot + 8 signed sums over this N-half
#pragma unroll
    for (int mt = 0; mt < 2; mt++) {
#pragma unroll
        for (int rh = 0; rh < 2; rh++) {
            int rowL = wm * 32 + mt * 16 + gid + rh * 8;
            float part[9];
#pragma unroll
            for (int j = 0; j < 9; j++) part[j] = 0.f;
#pragma unroll
            for (int nt = 0; nt < 4; nt++) {
#pragma unroll
                for (int j = 0; j < 2; j++) {
                    float vr = accR[mt][nt][rh * 2 + j];
                    float vi = accI[mt][nt][rh * 2 + j];
                    float p = vr * vr + vi * vi;
                    int s = half * 128 + wn * 32 + nt * 8 + 2 * tig + j;
                    part[0] += p;
#pragma unroll
                    for (int q = 0; q < 8; q++)
                        part[1 + q] += ((s >> (7 - q)) & 1) ? -p : p;
                }
            }
#pragma unroll
            for (int j = 0; j < 9; j++) {
                part[j] += __shfl_xor_sync(0xffffffffu, part[j], 1);
                part[j] += __shfl_xor_sync(0xffffffffu, part[j], 2);
            }
            if (tig == 0) {
#pragma unroll
                for (int j = 0; j < 9; j++)
                    atomicAdd(&red[rowL * 9 + j], part[j]);
            }
        }
    }
    __syncthreads();
    if (tid < 64) {
        float* dst = g_part + ((size_t)blockIdx.y * NB + bm + tid) * 9;
#pragma unroll
        for (int j = 0; j < 9; j++) dst[j] = red[tid * 9 + j];
    }
}

// ---------------------------------------------------------------------------
// Kernel 4: combine the two N-halves, normalize, write output
// ---------------------------------------------------------------------------
__global__ void __launch_bounds__(256) combine(float* __restrict__ out)
{
    int idx = blockIdx.x * 256 + threadIdx.x;   // 0 .. NB*NE-1
    int b = idx >> 4, e = idx & 15;
    const float* p0 = g_part + ((size_t)(e * 2 + 0) * NB + b) * 9;
    const float* p1 = g_part + ((size_t)(e * 2 + 1) * NB + b) * 9;
    float tot = p0[0] + p1[0];
    float inv = 1.0f / tot;
    float* o = out + (size_t)b * (NE * NQ) + e * NQ;
#pragma unroll
    for (int q = 0; q < 8; q++) o[q] = (p0[1 + q] + p1[1 + q]) * inv;
}

// ---------------------------------------------------------------------------
extern "C" void kernel_launch(void* const* d_in, const int* in_sizes, int n_in,
                              void* d_out, int out_size)
{
    const float* x  = (const float*)d_in[0];
    const float* pw = (const float*)d_in[1];
    const float* qw = (const float*)d_in[2];
    float* out = (float*)d_out;

    cudaFuncSetAttribute(gemm_mma, cudaFuncAttributeMaxDynamicSharedMemorySize, K2_SMEM);
    cudaFuncSetAttribute(qsim_mma, cudaFuncAttributeMaxDynamicSharedMemorySize, K3_SMEM);

    prep<<<3073, 256>>>(x, pw, qw);
    build_unitaries_reg<<<dim3(32, NE), 256>>>();
    gemm_mma<<<dim3(NWIDE / 128, NB / 128), 256, K2_SMEM>>>();
    qsim_mma<<<dim3(NB / 64, NE * 2), 256, K3_SMEM>>>();
    combine<<<NB * NE / 256, 256>>>(out);
}